// round 1
// baseline (speedup 1.0000x reference)
#include <cuda_runtime.h>
#include <math.h>
#include <float.h>

#define NN   8192
#define DIN  384
#define DH   512
#define KTOP 6
#define DH2  256
#define K7NODES 16

// ---------------- scratch (static device globals; no runtime allocation) ---
__device__ float g_x[NN * DH];
__device__ float g_eh[NN * DH];
__device__ float g_et[NN * DH];
__device__ float g_s1[NN * DH];
__device__ float g_s2[NN * DH];
__device__ float g_emb[NN * DH];
__device__ float g_mean[DH];
__device__ float g_part1[32 * DH];
__device__ float g_part2[32 * DH];
__device__ float g_topkw[NN * KTOP];
__device__ int   g_topki[NN * KTOP];
__device__ float g_a[NN];
__device__ float g_Z[1];

__device__ __forceinline__ float lrelu(float v) { return v > 0.0f ? v : 0.01f * v; }

// ---------------- K1: x = lrelu(x_s @ fc1_w + fc1_b) ----------------------
__global__ void k1_fc1(const float* __restrict__ A, const float* __restrict__ B,
                       const float* __restrict__ bias) {
    __shared__ float As[32][68];
    __shared__ float Bs[32][68];
    int bm = blockIdx.y * 64, bn = blockIdx.x * 64;
    int tid = threadIdx.x;
    int tx = tid & 15, ty = tid >> 4;
    float acc[4][4] = {};
    for (int k0 = 0; k0 < DIN; k0 += 32) {
        for (int i = tid; i < 64 * 32; i += 256) {
            int m = i >> 5, kk = i & 31;
            As[kk][m] = A[(bm + m) * DIN + k0 + kk];
        }
        for (int i = tid; i < 32 * 64; i += 256) {
            int kk = i >> 6, n = i & 63;
            Bs[kk][n] = B[(k0 + kk) * DH + bn + n];
        }
        __syncthreads();
#pragma unroll
        for (int kk = 0; kk < 32; kk++) {
            float4 a4 = *(const float4*)&As[kk][ty * 4];
            float4 b4 = *(const float4*)&Bs[kk][tx * 4];
            float av[4] = {a4.x, a4.y, a4.z, a4.w};
            float bv[4] = {b4.x, b4.y, b4.z, b4.w};
#pragma unroll
            for (int i = 0; i < 4; i++)
#pragma unroll
                for (int j = 0; j < 4; j++) acc[i][j] += av[i] * bv[j];
        }
        __syncthreads();
    }
#pragma unroll
    for (int i = 0; i < 4; i++) {
        int m = bm + ty * 4 + i;
#pragma unroll
        for (int j = 0; j < 4; j++) {
            int n = bn + tx * 4 + j;
            g_x[m * DH + n] = lrelu(acc[i][j] + bias[n]);
        }
    }
}

// ---------------- K2: column mean of x (deterministic two-stage) ----------
__global__ void k2_colpart() {
    int c = blockIdx.x * 256 + threadIdx.x;
    int r0 = blockIdx.y * 256;
    float s = 0.0f;
    for (int i = 0; i < 256; i++) s += g_x[(r0 + i) * DH + c];
    g_part1[blockIdx.y * DH + c] = s;
}

__global__ void k2b_colmean() {
    int c = threadIdx.x;
    float s = 0.0f;
    for (int p = 0; p < 32; p++) s += g_part1[p * DH + c];
    g_mean[c] = s * (1.0f / NN);
}

// ---------------- K3: e_h = xm@wh + bh ; e_t = xm@wt + bt ------------------
// xm = (x + mean)*0.5 applied on the fly during A-tile loads.
__global__ void k3_dual(const float* __restrict__ B1, const float* __restrict__ b1,
                        const float* __restrict__ B2, const float* __restrict__ b2) {
    __shared__ float As[32][68];
    __shared__ float B1s[32][68];
    __shared__ float B2s[32][68];
    int bm = blockIdx.y * 64, bn = blockIdx.x * 64;
    int tid = threadIdx.x;
    int tx = tid & 15, ty = tid >> 4;
    float acc1[4][4] = {}, acc2[4][4] = {};
    for (int k0 = 0; k0 < DH; k0 += 32) {
        for (int i = tid; i < 64 * 32; i += 256) {
            int m = i >> 5, kk = i & 31;
            int col = k0 + kk;
            As[kk][m] = (g_x[(bm + m) * DH + col] + g_mean[col]) * 0.5f;
        }
        for (int i = tid; i < 32 * 64; i += 256) {
            int kk = i >> 6, n = i & 63;
            B1s[kk][n] = B1[(k0 + kk) * DH + bn + n];
            B2s[kk][n] = B2[(k0 + kk) * DH + bn + n];
        }
        __syncthreads();
#pragma unroll
        for (int kk = 0; kk < 32; kk++) {
            float4 a4 = *(const float4*)&As[kk][ty * 4];
            float4 p4 = *(const float4*)&B1s[kk][tx * 4];
            float4 q4 = *(const float4*)&B2s[kk][tx * 4];
            float av[4] = {a4.x, a4.y, a4.z, a4.w};
            float pv[4] = {p4.x, p4.y, p4.z, p4.w};
            float qv[4] = {q4.x, q4.y, q4.z, q4.w};
#pragma unroll
            for (int i = 0; i < 4; i++)
#pragma unroll
                for (int j = 0; j < 4; j++) {
                    acc1[i][j] += av[i] * pv[j];
                    acc2[i][j] += av[i] * qv[j];
                }
        }
        __syncthreads();
    }
#pragma unroll
    for (int i = 0; i < 4; i++) {
        int m = bm + ty * 4 + i;
#pragma unroll
        for (int j = 0; j < 4; j++) {
            int n = bn + tx * 4 + j;
            g_eh[m * DH + n] = acc1[i][j] + b1[n];
            g_et[m * DH + n] = acc2[i][j] + b2[n];
        }
    }
}

// ---------------- K4: fused scores GEMM + online top-6 ---------------------
// score[i][j] = scale * dot(e_h[i], e_t[j]); keep per-row top-6 (stable: ties
// -> earlier index, matching jax.lax.top_k) without materializing NxN.
__global__ void k4_attn_topk() {
    __shared__ float As[32][68];
    __shared__ float Bs[32][68];
    __shared__ float Ssc[64][65];
    const float scale = 0.044194173824159216f;  // 512^-0.5
    int bm = blockIdx.x * 64;
    int tid = threadIdx.x;
    int tx = tid & 15, ty = tid >> 4;
    float tv[KTOP];
    int ti[KTOP];
#pragma unroll
    for (int k = 0; k < KTOP; k++) { tv[k] = -FLT_MAX; ti[k] = 0; }

    for (int bn = 0; bn < NN; bn += 64) {
        float acc[4][4] = {};
        for (int k0 = 0; k0 < DH; k0 += 32) {
            for (int i = tid; i < 64 * 32; i += 256) {
                int m = i >> 5, kk = i & 31;
                As[kk][m] = g_eh[(bm + m) * DH + k0 + kk];
                Bs[kk][m] = g_et[(bn + m) * DH + k0 + kk];
            }
            __syncthreads();
#pragma unroll
            for (int kk = 0; kk < 32; kk++) {
                float4 a4 = *(const float4*)&As[kk][ty * 4];
                float4 b4 = *(const float4*)&Bs[kk][tx * 4];
                float av[4] = {a4.x, a4.y, a4.z, a4.w};
                float bv[4] = {b4.x, b4.y, b4.z, b4.w};
#pragma unroll
                for (int i = 0; i < 4; i++)
#pragma unroll
                    for (int j = 0; j < 4; j++) acc[i][j] += av[i] * bv[j];
            }
            __syncthreads();
        }
#pragma unroll
        for (int i = 0; i < 4; i++)
#pragma unroll
            for (int j = 0; j < 4; j++)
                Ssc[ty * 4 + i][tx * 4 + j] = acc[i][j] * scale;
        __syncthreads();
        if (tid < 64) {
#pragma unroll 1
            for (int j = 0; j < 64; j++) {
                float v = Ssc[tid][j];
                if (v > tv[KTOP - 1]) {
                    tv[KTOP - 1] = v;
                    ti[KTOP - 1] = bn + j;
#pragma unroll
                    for (int p = KTOP - 1; p > 0; p--) {
                        if (tv[p] > tv[p - 1]) {
                            float tf = tv[p]; tv[p] = tv[p - 1]; tv[p - 1] = tf;
                            int tt = ti[p]; ti[p] = ti[p - 1]; ti[p - 1] = tt;
                        }
                    }
                }
            }
        }
        __syncthreads();
    }
    if (tid < 64) {
#pragma unroll
        for (int k = 0; k < KTOP; k++) {
            g_topkw[(bm + tid) * KTOP + k] = tv[k];
            g_topki[(bm + tid) * KTOP + k] = ti[k];
        }
    }
}

// ---------------- K5: per-node neighbor aggregation -> s1, s2 --------------
__global__ void __launch_bounds__(256) k5_neigh() {
    int node = (blockIdx.x * 256 + threadIdx.x) >> 5;
    int lane = threadIdx.x & 31;
    if (node >= NN) return;

    float w[KTOP];
    int idx[KTOP];
#pragma unroll
    for (int k = 0; k < KTOP; k++) {
        w[k] = g_topkw[node * KTOP + k];
        idx[k] = g_topki[node * KTOP + k];
    }
    // softmax over top-k weights (w[0] is the max: list is sorted desc)
    float p[KTOP], ps = 0.0f;
#pragma unroll
    for (int k = 0; k < KTOP; k++) { p[k] = expf(w[k] - w[0]); ps += p[k]; }
    float pinv = 1.0f / ps;
#pragma unroll
    for (int k = 0; k < KTOP; k++) p[k] *= pinv;

    float ehv[16], nb[KTOP][16];
#pragma unroll
    for (int t = 0; t < 16; t++) ehv[t] = g_eh[node * DH + lane + t * 32];
#pragma unroll
    for (int k = 0; k < KTOP; k++)
#pragma unroll
        for (int t = 0; t < 16; t++)
            nb[k][t] = g_et[idx[k] * DH + lane + t * 32];

    float ka[KTOP];
#pragma unroll
    for (int k = 0; k < KTOP; k++) {
        float s = 0.0f;
#pragma unroll
        for (int t = 0; t < 16; t++) {
            float ehr  = p[k] * nb[k][t] + (1.0f - p[k]) * ehv[t];
            float gate = tanhf(ehv[t] + ehr);
            s += nb[k][t] * gate;
        }
#pragma unroll
        for (int o = 16; o > 0; o >>= 1) s += __shfl_xor_sync(0xffffffffu, s, o);
        ka[k] = s;
    }
    float km = ka[0];
#pragma unroll
    for (int k = 1; k < KTOP; k++) km = fmaxf(km, ka[k]);
    float kp[KTOP], ks = 0.0f;
#pragma unroll
    for (int k = 0; k < KTOP; k++) { kp[k] = expf(ka[k] - km); ks += kp[k]; }
    float kinv = 1.0f / ks;
#pragma unroll
    for (int k = 0; k < KTOP; k++) kp[k] *= kinv;

#pragma unroll
    for (int t = 0; t < 16; t++) {
        float enh = 0.0f;
#pragma unroll
        for (int k = 0; k < KTOP; k++) enh += kp[k] * nb[k][t];
        int d = lane + t * 32;
        g_s1[node * DH + d] = ehv[t] + enh;
        g_s2[node * DH + d] = ehv[t] * enh;
    }
}

// ---------------- K6: emb = lrelu(s1@l1+b1) + lrelu(s2@l2+b2) --------------
__global__ void k6_dual(const float* __restrict__ B1, const float* __restrict__ b1,
                        const float* __restrict__ B2, const float* __restrict__ b2) {
    __shared__ float A1s[32][68];
    __shared__ float A2s[32][68];
    __shared__ float B1s[32][68];
    __shared__ float B2s[32][68];
    int bm = blockIdx.y * 64, bn = blockIdx.x * 64;
    int tid = threadIdx.x;
    int tx = tid & 15, ty = tid >> 4;
    float acc1[4][4] = {}, acc2[4][4] = {};
    for (int k0 = 0; k0 < DH; k0 += 32) {
        for (int i = tid; i < 64 * 32; i += 256) {
            int m = i >> 5, kk = i & 31;
            A1s[kk][m] = g_s1[(bm + m) * DH + k0 + kk];
            A2s[kk][m] = g_s2[(bm + m) * DH + k0 + kk];
        }
        for (int i = tid; i < 32 * 64; i += 256) {
            int kk = i >> 6, n = i & 63;
            B1s[kk][n] = B1[(k0 + kk) * DH + bn + n];
            B2s[kk][n] = B2[(k0 + kk) * DH + bn + n];
        }
        __syncthreads();
#pragma unroll
        for (int kk = 0; kk < 32; kk++) {
            float4 a14 = *(const float4*)&A1s[kk][ty * 4];
            float4 a24 = *(const float4*)&A2s[kk][ty * 4];
            float4 p4  = *(const float4*)&B1s[kk][tx * 4];
            float4 q4  = *(const float4*)&B2s[kk][tx * 4];
            float a1v[4] = {a14.x, a14.y, a14.z, a14.w};
            float a2v[4] = {a24.x, a24.y, a24.z, a24.w};
            float pv[4]  = {p4.x, p4.y, p4.z, p4.w};
            float qv[4]  = {q4.x, q4.y, q4.z, q4.w};
#pragma unroll
            for (int i = 0; i < 4; i++)
#pragma unroll
                for (int j = 0; j < 4; j++) {
                    acc1[i][j] += a1v[i] * pv[j];
                    acc2[i][j] += a2v[i] * qv[j];
                }
        }
        __syncthreads();
    }
#pragma unroll
    for (int i = 0; i < 4; i++) {
        int m = bm + ty * 4 + i;
#pragma unroll
        for (int j = 0; j < 4; j++) {
            int n = bn + tx * 4 + j;
            g_emb[m * DH + n] = lrelu(acc1[i][j] + b1[n]) + lrelu(acc2[i][j] + b2[n]);
        }
    }
}

// ---------------- K7: node scores a = lrelu(emb@att1+b)@att2+b -------------
__global__ void k7_readout(const float* __restrict__ att1_w, const float* __restrict__ att1_b,
                           const float* __restrict__ att2_w, const float* __restrict__ att2_b) {
    __shared__ float se[K7NODES][DH];
    __shared__ float warpred[8];
    int n0 = blockIdx.x * K7NODES;
    int tid = threadIdx.x;
    for (int i = tid; i < K7NODES * DH; i += 256)
        se[i >> 9][i & 511] = g_emb[(n0 + (i >> 9)) * DH + (i & 511)];
    __syncthreads();

    int j = tid;  // hidden unit 0..255
    float acc[K7NODES];
#pragma unroll
    for (int m = 0; m < K7NODES; m++) acc[m] = 0.0f;

    for (int d = 0; d < DH; d += 4) {
        float w0 = att1_w[(d + 0) * DH2 + j];
        float w1 = att1_w[(d + 1) * DH2 + j];
        float w2 = att1_w[(d + 2) * DH2 + j];
        float w3 = att1_w[(d + 3) * DH2 + j];
#pragma unroll
        for (int m = 0; m < K7NODES; m++) {
            float4 e = *(const float4*)&se[m][d];
            acc[m] += e.x * w0 + e.y * w1 + e.z * w2 + e.w * w3;
        }
    }
    float b1 = att1_b[j], a2 = att2_w[j], b2v = att2_b[0];
    int lane = tid & 31, wid = tid >> 5;
    for (int m = 0; m < K7NODES; m++) {
        float v = lrelu(acc[m] + b1) * a2;
#pragma unroll
        for (int o = 16; o > 0; o >>= 1) v += __shfl_xor_sync(0xffffffffu, v, o);
        if (lane == 0) warpred[wid] = v;
        __syncthreads();
        if (tid == 0) {
            float s = 0.0f;
            for (int q = 0; q < 8; q++) s += warpred[q];
            g_a[n0 + m] = s + b2v;
        }
        __syncthreads();
    }
}

// ---------------- K8: softmax over nodes (in place: g_a <- exp(a-amax)) ----
__global__ void k8_softmax() {
    __shared__ float red[1024];
    int tid = threadIdx.x;
    float lm = -FLT_MAX;
    for (int i = tid; i < NN; i += 1024) lm = fmaxf(lm, g_a[i]);
    red[tid] = lm;
    __syncthreads();
    for (int s = 512; s > 0; s >>= 1) {
        if (tid < s) red[tid] = fmaxf(red[tid], red[tid + s]);
        __syncthreads();
    }
    float amax = red[0];
    __syncthreads();
    float ls = 0.0f;
    for (int i = tid; i < NN; i += 1024) {
        float w = expf(g_a[i] - amax);
        g_a[i] = w;
        ls += w;
    }
    red[tid] = ls;
    __syncthreads();
    for (int s = 512; s > 0; s >>= 1) {
        if (tid < s) red[tid] += red[tid + s];
        __syncthreads();
    }
    if (tid == 0) g_Z[0] = red[0];
}

// ---------------- K9: partial weighted sums over nodes ---------------------
__global__ void k9_wsum() {
    int d = blockIdx.x * 128 + threadIdx.x;
    int r0 = blockIdx.y * 256;
    float s = 0.0f;
    for (int i = 0; i < 256; i++) s += g_a[r0 + i] * g_emb[(r0 + i) * DH + d];
    g_part2[blockIdx.y * DH + d] = s;
}

// ---------------- K10: finalize: h, layernorm, logits ----------------------
__global__ void k10_final(const float* __restrict__ ln_g, const float* __restrict__ ln_b,
                          const float* __restrict__ fc_w, const float* __restrict__ fc_b,
                          float* __restrict__ out) {
    __shared__ float red[DH];
    int tid = threadIdx.x;
    float raw = 0.0f;
    for (int p = 0; p < 32; p++) raw += g_part2[p * DH + tid];
    float h = raw / g_Z[0];

    red[tid] = h;
    __syncthreads();
    for (int s = 256; s > 0; s >>= 1) {
        if (tid < s) red[tid] += red[tid + s];
        __syncthreads();
    }
    float mu = red[0] * (1.0f / DH);
    __syncthreads();
    float dv = h - mu;
    red[tid] = dv * dv;
    __syncthreads();
    for (int s = 256; s > 0; s >>= 1) {
        if (tid < s) red[tid] += red[tid + s];
        __syncthreads();
    }
    float var = red[0] * (1.0f / DH);
    __syncthreads();
    float hn = dv * rsqrtf(var + 1e-5f) * ln_g[tid] + ln_b[tid];

    float p0 = hn * fc_w[tid * 2 + 0];
    float p1 = hn * fc_w[tid * 2 + 1];
    red[tid] = p0;
    __syncthreads();
    for (int s = 256; s > 0; s >>= 1) {
        if (tid < s) red[tid] += red[tid + s];
        __syncthreads();
    }
    float s0 = red[0];
    __syncthreads();
    red[tid] = p1;
    __syncthreads();
    for (int s = 256; s > 0; s >>= 1) {
        if (tid < s) red[tid] += red[tid + s];
        __syncthreads();
    }
    if (tid == 0) {
        out[0] = s0 + fc_b[0];
        out[1] = red[0] + fc_b[1];
    }
}

// ---------------- launch ---------------------------------------------------
extern "C" void kernel_launch(void* const* d_in, const int* in_sizes, int n_in,
                              void* d_out, int out_size) {
    (void)in_sizes; (void)n_in; (void)out_size;
    const float* x_s    = (const float*)d_in[0];
    const float* fc1_w  = (const float*)d_in[1];
    const float* fc1_b  = (const float*)d_in[2];
    const float* wh_w   = (const float*)d_in[3];
    const float* wh_b   = (const float*)d_in[4];
    const float* wt_w   = (const float*)d_in[5];
    const float* wt_b   = (const float*)d_in[6];
    const float* l1_w   = (const float*)d_in[7];
    const float* l1_b   = (const float*)d_in[8];
    const float* l2_w   = (const float*)d_in[9];
    const float* l2_b   = (const float*)d_in[10];
    const float* att1_w = (const float*)d_in[11];
    const float* att1_b = (const float*)d_in[12];
    const float* att2_w = (const float*)d_in[13];
    const float* att2_b = (const float*)d_in[14];
    const float* ln_g   = (const float*)d_in[15];
    const float* ln_b   = (const float*)d_in[16];
    const float* fc_w   = (const float*)d_in[17];
    const float* fc_b   = (const float*)d_in[18];
    float* out = (float*)d_out;

    dim3 gg(DH / 64, NN / 64);
    k1_fc1<<<gg, 256>>>(x_s, fc1_w, fc1_b);
    k2_colpart<<<dim3(2, 32), 256>>>();
    k2b_colmean<<<1, DH>>>();
    k3_dual<<<gg, 256>>>(wh_w, wh_b, wt_w, wt_b);
    k4_attn_topk<<<NN / 64, 256>>>();
    k5_neigh<<<NN / 8, 256>>>();
    k6_dual<<<gg, 256>>>(l1_w, l1_b, l2_w, l2_b);
    k7_readout<<<NN / K7NODES, 256>>>(att1_w, att1_b, att2_w, att2_b);
    k8_softmax<<<1, 1024>>>();
    k9_wsum<<<dim3(4, 32), 128>>>();
    k10_final<<<1, DH>>>(ln_g, ln_b, fc_w, fc_b, out);
}

// round 2
// speedup vs baseline: 3.8653x; 3.8653x over previous
#include <cuda_runtime.h>
#include <cuda_bf16.h>
#include <math.h>
#include <float.h>
#include <stdint.h>

#define NN   8192
#define DIN  384
#define DH   512
#define KTOP 6
#define DH2  256
#define K7NODES 16
#define NCAND 24

// ---------------- scratch (static device globals; no runtime allocation) ---
__device__ float g_x[NN * DH];
__device__ float g_eh[NN * DH];
__device__ float g_et[NN * DH];
__device__ __nv_bfloat16 g_ehb[NN * DH];
__device__ __nv_bfloat16 g_etb[NN * DH];
__device__ float g_s1[NN * DH];
__device__ float g_s2[NN * DH];
__device__ float g_emb[NN * DH];
__device__ float g_mean[DH];
__device__ float g_part1[32 * DH];
__device__ float g_part2[32 * DH];
__device__ float g_topkw[NN * KTOP];
__device__ int   g_topki[NN * KTOP];
__device__ int   g_candi[NN * NCAND];
__device__ float g_a[NN];
__device__ float g_Z[1];

__device__ __forceinline__ float lrelu(float v) { return v > 0.0f ? v : 0.01f * v; }

__device__ __forceinline__ uint32_t saddr(const void* p) {
    return (uint32_t)__cvta_generic_to_shared(p);
}

__device__ __forceinline__ void ldsm4(unsigned r[4], uint32_t addr) {
    asm volatile("ldmatrix.sync.aligned.m8n8.x4.shared.b16 {%0,%1,%2,%3}, [%4];"
                 : "=r"(r[0]), "=r"(r[1]), "=r"(r[2]), "=r"(r[3]) : "r"(addr));
}

__device__ __forceinline__ void mma_bf16(float* d, unsigned a0, unsigned a1,
                                         unsigned a2, unsigned a3,
                                         unsigned b0, unsigned b1) {
    asm volatile("mma.sync.aligned.m16n8k16.row.col.f32.bf16.bf16.f32 "
                 "{%0,%1,%2,%3}, {%4,%5,%6,%7}, {%8,%9}, {%0,%1,%2,%3};"
                 : "+f"(d[0]), "+f"(d[1]), "+f"(d[2]), "+f"(d[3])
                 : "r"(a0), "r"(a1), "r"(a2), "r"(a3), "r"(b0), "r"(b1));
}

// ---------------- K1: x = lrelu(x_s @ fc1_w + fc1_b) ----------------------
__global__ void k1_fc1(const float* __restrict__ A, const float* __restrict__ B,
                       const float* __restrict__ bias) {
    __shared__ float As[32][68];
    __shared__ float Bs[32][68];
    int bm = blockIdx.y * 64, bn = blockIdx.x * 64;
    int tid = threadIdx.x;
    int tx = tid & 15, ty = tid >> 4;
    float acc[4][4] = {};
    for (int k0 = 0; k0 < DIN; k0 += 32) {
        for (int i = tid; i < 64 * 32; i += 256) {
            int m = i >> 5, kk = i & 31;
            As[kk][m] = A[(bm + m) * DIN + k0 + kk];
        }
        for (int i = tid; i < 32 * 64; i += 256) {
            int kk = i >> 6, n = i & 63;
            Bs[kk][n] = B[(k0 + kk) * DH + bn + n];
        }
        __syncthreads();
#pragma unroll
        for (int kk = 0; kk < 32; kk++) {
            float4 a4 = *(const float4*)&As[kk][ty * 4];
            float4 b4 = *(const float4*)&Bs[kk][tx * 4];
            float av[4] = {a4.x, a4.y, a4.z, a4.w};
            float bv[4] = {b4.x, b4.y, b4.z, b4.w};
#pragma unroll
            for (int i = 0; i < 4; i++)
#pragma unroll
                for (int j = 0; j < 4; j++) acc[i][j] += av[i] * bv[j];
        }
        __syncthreads();
    }
#pragma unroll
    for (int i = 0; i < 4; i++) {
        int m = bm + ty * 4 + i;
#pragma unroll
        for (int j = 0; j < 4; j++) {
            int n = bn + tx * 4 + j;
            g_x[m * DH + n] = lrelu(acc[i][j] + bias[n]);
        }
    }
}

// ---------------- K2: column mean of x (deterministic two-stage) ----------
__global__ void k2_colpart() {
    int c = blockIdx.x * 256 + threadIdx.x;
    int r0 = blockIdx.y * 256;
    float s = 0.0f;
    for (int i = 0; i < 256; i++) s += g_x[(r0 + i) * DH + c];
    g_part1[blockIdx.y * DH + c] = s;
}

__global__ void k2b_colmean() {
    int c = threadIdx.x;
    float s = 0.0f;
    for (int p = 0; p < 32; p++) s += g_part1[p * DH + c];
    g_mean[c] = s * (1.0f / NN);
}

// ---------------- K3: e_h = xm@wh + bh ; e_t = xm@wt + bt ------------------
__global__ void k3_dual(const float* __restrict__ B1, const float* __restrict__ b1,
                        const float* __restrict__ B2, const float* __restrict__ b2) {
    __shared__ float As[32][68];
    __shared__ float B1s[32][68];
    __shared__ float B2s[32][68];
    int bm = blockIdx.y * 64, bn = blockIdx.x * 64;
    int tid = threadIdx.x;
    int tx = tid & 15, ty = tid >> 4;
    float acc1[4][4] = {}, acc2[4][4] = {};
    for (int k0 = 0; k0 < DH; k0 += 32) {
        for (int i = tid; i < 64 * 32; i += 256) {
            int m = i >> 5, kk = i & 31;
            int col = k0 + kk;
            As[kk][m] = (g_x[(bm + m) * DH + col] + g_mean[col]) * 0.5f;
        }
        for (int i = tid; i < 32 * 64; i += 256) {
            int kk = i >> 6, n = i & 63;
            B1s[kk][n] = B1[(k0 + kk) * DH + bn + n];
            B2s[kk][n] = B2[(k0 + kk) * DH + bn + n];
        }
        __syncthreads();
#pragma unroll
        for (int kk = 0; kk < 32; kk++) {
            float4 a4 = *(const float4*)&As[kk][ty * 4];
            float4 p4 = *(const float4*)&B1s[kk][tx * 4];
            float4 q4 = *(const float4*)&B2s[kk][tx * 4];
            float av[4] = {a4.x, a4.y, a4.z, a4.w};
            float pv[4] = {p4.x, p4.y, p4.z, p4.w};
            float qv[4] = {q4.x, q4.y, q4.z, q4.w};
#pragma unroll
            for (int i = 0; i < 4; i++)
#pragma unroll
                for (int j = 0; j < 4; j++) {
                    acc1[i][j] += av[i] * pv[j];
                    acc2[i][j] += av[i] * qv[j];
                }
        }
        __syncthreads();
    }
#pragma unroll
    for (int i = 0; i < 4; i++) {
        int m = bm + ty * 4 + i;
#pragma unroll
        for (int j = 0; j < 4; j++) {
            int n = bn + tx * 4 + j;
            float v1 = acc1[i][j] + b1[n];
            float v2 = acc2[i][j] + b2[n];
            g_eh[m * DH + n] = v1;
            g_et[m * DH + n] = v2;
            g_ehb[m * DH + n] = __float2bfloat16(v1);
            g_etb[m * DH + n] = __float2bfloat16(v2);
        }
    }
}

// ---------------- K4: tensor-core score GEMM + candidate top-6 -------------
// Each block owns 64 rows; streams all 8192 columns in 128-wide tiles with
// bf16 HMMA (fp32 accum). 4 threads per row keep their quarter's top-6 -> 24
// candidate indices/row, refined to exact fp32 top-6 in k4b.
#define ASTRIDE 520
#define BSTRIDE 72
#define SSTRIDE 132
#define SMEM_A_BYTES (64 * ASTRIDE * 2)          // 66560
#define SMEM_B_BYTES (128 * BSTRIDE * 2)         // 18432
#define SMEM_S_BYTES (64 * SSTRIDE * 4)          // 33792
#define SMEM4_TOTAL (SMEM_A_BYTES + SMEM_B_BYTES + SMEM_S_BYTES)

__global__ void __launch_bounds__(256, 1) k4_tc() {
    extern __shared__ char sm4[];
    __nv_bfloat16* As = (__nv_bfloat16*)sm4;
    __nv_bfloat16* Bs = (__nv_bfloat16*)(sm4 + SMEM_A_BYTES);
    float* Ssc = (float*)(sm4 + SMEM_A_BYTES + SMEM_B_BYTES);

    int tid = threadIdx.x;
    int warp = tid >> 5, lane = tid & 31;
    int wm = warp & 1, wn = warp >> 1;
    int bm = blockIdx.x * 64;
    int lrow = lane & 15, lkoff = (lane >> 4) * 8;
    int g = lane >> 2, tg = lane & 3;
    int myrow = tid >> 2, myq = tid & 3;

    // Load A stripe (64 x 512) once.
    for (int i = tid; i < 64 * 64; i += 256) {
        int row = i >> 6, c4 = i & 63;
        *(uint4*)(As + row * ASTRIDE + c4 * 8) =
            *(const uint4*)(g_ehb + (size_t)(bm + row) * DH + c4 * 8);
    }

    float tv[KTOP];
    int ti[KTOP];
#pragma unroll
    for (int k = 0; k < KTOP; k++) { tv[k] = -FLT_MAX; ti[k] = 0; }

    const float scale = 0.044194173824159216f;

    for (int bn = 0; bn < NN; bn += 128) {
        float acc[2][4][4];
#pragma unroll
        for (int a = 0; a < 2; a++)
#pragma unroll
            for (int b = 0; b < 4; b++)
#pragma unroll
                for (int c = 0; c < 4; c++) acc[a][b][c] = 0.0f;

        for (int ch = 0; ch < 8; ch++) {
            __syncthreads();
            // load B chunk: 128 rows x 64 k (bf16)
            for (int i = tid; i < 1024; i += 256) {
                int row = i >> 3, c4 = i & 7;
                *(uint4*)(Bs + row * BSTRIDE + c4 * 8) =
                    *(const uint4*)(g_etb + (size_t)(bn + row) * DH + ch * 64 + c4 * 8);
            }
            __syncthreads();
#pragma unroll
            for (int ks = 0; ks < 4; ks++) {
                unsigned a0[4], a1[4], b0[4], b1[4];
                int kA = ch * 64 + ks * 16 + lkoff;
                ldsm4(a0, saddr(&As[(wm * 32 + lrow) * ASTRIDE + kA]));
                ldsm4(a1, saddr(&As[(wm * 32 + 16 + lrow) * ASTRIDE + kA]));
                int kB = ks * 16 + lkoff;
                ldsm4(b0, saddr(&Bs[(wn * 32 + lrow) * BSTRIDE + kB]));
                ldsm4(b1, saddr(&Bs[(wn * 32 + 16 + lrow) * BSTRIDE + kB]));
                mma_bf16(acc[0][0], a0[0], a0[1], a0[2], a0[3], b0[0], b0[2]);
                mma_bf16(acc[0][1], a0[0], a0[1], a0[2], a0[3], b0[1], b0[3]);
                mma_bf16(acc[0][2], a0[0], a0[1], a0[2], a0[3], b1[0], b1[2]);
                mma_bf16(acc[0][3], a0[0], a0[1], a0[2], a0[3], b1[1], b1[3]);
                mma_bf16(acc[1][0], a1[0], a1[1], a1[2], a1[3], b0[0], b0[2]);
                mma_bf16(acc[1][1], a1[0], a1[1], a1[2], a1[3], b0[1], b0[3]);
                mma_bf16(acc[1][2], a1[0], a1[1], a1[2], a1[3], b1[0], b1[2]);
                mma_bf16(acc[1][3], a1[0], a1[1], a1[2], a1[3], b1[1], b1[3]);
            }
        }
        __syncthreads();
#pragma unroll
        for (int msub = 0; msub < 2; msub++) {
            int row0 = wm * 32 + msub * 16 + g;
#pragma unroll
            for (int nsub = 0; nsub < 4; nsub++) {
                int col = wn * 32 + nsub * 8 + tg * 2;
                Ssc[row0 * SSTRIDE + col]           = acc[msub][nsub][0];
                Ssc[row0 * SSTRIDE + col + 1]       = acc[msub][nsub][1];
                Ssc[(row0 + 8) * SSTRIDE + col]     = acc[msub][nsub][2];
                Ssc[(row0 + 8) * SSTRIDE + col + 1] = acc[msub][nsub][3];
            }
        }
        __syncthreads();
#pragma unroll 1
        for (int j = 0; j < 32; j++) {
            float v = Ssc[myrow * SSTRIDE + myq * 32 + j] * scale;
            if (v > tv[KTOP - 1]) {
                tv[KTOP - 1] = v;
                ti[KTOP - 1] = bn + myq * 32 + j;
#pragma unroll
                for (int p = KTOP - 1; p > 0; p--) {
                    if (tv[p] > tv[p - 1]) {
                        float tf = tv[p]; tv[p] = tv[p - 1]; tv[p - 1] = tf;
                        int tt = ti[p]; ti[p] = ti[p - 1]; ti[p - 1] = tt;
                    }
                }
            }
        }
    }
#pragma unroll
    for (int k = 0; k < KTOP; k++)
        g_candi[(size_t)(bm + myrow) * NCAND + myq * KTOP + k] = ti[k];
}

// ---------------- K4b: exact fp32 refinement of 24 candidates -> top-6 -----
__global__ void __launch_bounds__(256) k4b_refine() {
    int node = blockIdx.x * 8 + (threadIdx.x >> 5);
    int lane = threadIdx.x & 31;
    const float scale = 0.044194173824159216f;

    float eh[16];
#pragma unroll
    for (int t = 0; t < 16; t++) eh[t] = g_eh[(size_t)node * DH + lane + t * 32];

    float vals[NCAND];
    int idxs[NCAND];
#pragma unroll
    for (int c = 0; c < NCAND; c++) {
        int idx = g_candi[(size_t)node * NCAND + c];
        idxs[c] = idx;
        const float* et = g_et + (size_t)idx * DH;
        float s = 0.0f;
#pragma unroll
        for (int t = 0; t < 16; t++) s += eh[t] * et[lane + t * 32];
#pragma unroll
        for (int o = 16; o > 0; o >>= 1) s += __shfl_xor_sync(0xffffffffu, s, o);
        vals[c] = s * scale;
    }

    unsigned used = 0;
#pragma unroll
    for (int p = 0; p < KTOP; p++) {
        float bv = -FLT_MAX; int bi = 0x7fffffff; int bc = 0;
#pragma unroll
        for (int c = 0; c < NCAND; c++) {
            if (!((used >> c) & 1u)) {
                if (vals[c] > bv || (vals[c] == bv && idxs[c] < bi)) {
                    bv = vals[c]; bi = idxs[c]; bc = c;
                }
            }
        }
        used |= 1u << bc;
        if (lane == 0) {
            g_topkw[node * KTOP + p] = bv;
            g_topki[node * KTOP + p] = bi;
        }
    }
}

// ---------------- K5: per-node neighbor aggregation -> s1, s2 --------------
__global__ void __launch_bounds__(256) k5_neigh() {
    int node = (blockIdx.x * 256 + threadIdx.x) >> 5;
    int lane = threadIdx.x & 31;
    if (node >= NN) return;

    float w[KTOP];
    int idx[KTOP];
#pragma unroll
    for (int k = 0; k < KTOP; k++) {
        w[k] = g_topkw[node * KTOP + k];
        idx[k] = g_topki[node * KTOP + k];
    }
    float p[KTOP], ps = 0.0f;
#pragma unroll
    for (int k = 0; k < KTOP; k++) { p[k] = expf(w[k] - w[0]); ps += p[k]; }
    float pinv = 1.0f / ps;
#pragma unroll
    for (int k = 0; k < KTOP; k++) p[k] *= pinv;

    float ehv[16], nb[KTOP][16];
#pragma unroll
    for (int t = 0; t < 16; t++) ehv[t] = g_eh[node * DH + lane + t * 32];
#pragma unroll
    for (int k = 0; k < KTOP; k++)
#pragma unroll
        for (int t = 0; t < 16; t++)
            nb[k][t] = g_et[idx[k] * DH + lane + t * 32];

    float ka[KTOP];
#pragma unroll
    for (int k = 0; k < KTOP; k++) {
        float s = 0.0f;
#pragma unroll
        for (int t = 0; t < 16; t++) {
            float ehr  = p[k] * nb[k][t] + (1.0f - p[k]) * ehv[t];
            float gate = tanhf(ehv[t] + ehr);
            s += nb[k][t] * gate;
        }
#pragma unroll
        for (int o = 16; o > 0; o >>= 1) s += __shfl_xor_sync(0xffffffffu, s, o);
        ka[k] = s;
    }
    float km = ka[0];
#pragma unroll
    for (int k = 1; k < KTOP; k++) km = fmaxf(km, ka[k]);
    float kp[KTOP], ks = 0.0f;
#pragma unroll
    for (int k = 0; k < KTOP; k++) { kp[k] = expf(ka[k] - km); ks += kp[k]; }
    float kinv = 1.0f / ks;
#pragma unroll
    for (int k = 0; k < KTOP; k++) kp[k] *= kinv;

#pragma unroll
    for (int t = 0; t < 16; t++) {
        float enh = 0.0f;
#pragma unroll
        for (int k = 0; k < KTOP; k++) enh += kp[k] * nb[k][t];
        int d = lane + t * 32;
        g_s1[node * DH + d] = ehv[t] + enh;
        g_s2[node * DH + d] = ehv[t] * enh;
    }
}

// ---------------- K6: emb = lrelu(s1@l1+b1) + lrelu(s2@l2+b2) --------------
__global__ void k6_dual(const float* __restrict__ B1, const float* __restrict__ b1,
                        const float* __restrict__ B2, const float* __restrict__ b2) {
    __shared__ float A1s[32][68];
    __shared__ float A2s[32][68];
    __shared__ float B1s[32][68];
    __shared__ float B2s[32][68];
    int bm = blockIdx.y * 64, bn = blockIdx.x * 64;
    int tid = threadIdx.x;
    int tx = tid & 15, ty = tid >> 4;
    float acc1[4][4] = {}, acc2[4][4] = {};
    for (int k0 = 0; k0 < DH; k0 += 32) {
        for (int i = tid; i < 64 * 32; i += 256) {
            int m = i >> 5, kk = i & 31;
            A1s[kk][m] = g_s1[(bm + m) * DH + k0 + kk];
            A2s[kk][m] = g_s2[(bm + m) * DH + k0 + kk];
        }
        for (int i = tid; i < 32 * 64; i += 256) {
            int kk = i >> 6, n = i & 63;
            B1s[kk][n] = B1[(k0 + kk) * DH + bn + n];
            B2s[kk][n] = B2[(k0 + kk) * DH + bn + n];
        }
        __syncthreads();
#pragma unroll
        for (int kk = 0; kk < 32; kk++) {
            float4 a14 = *(const float4*)&A1s[kk][ty * 4];
            float4 a24 = *(const float4*)&A2s[kk][ty * 4];
            float4 p4  = *(const float4*)&B1s[kk][tx * 4];
            float4 q4  = *(const float4*)&B2s[kk][tx * 4];
            float a1v[4] = {a14.x, a14.y, a14.z, a14.w};
            float a2v[4] = {a24.x, a24.y, a24.z, a24.w};
            float pv[4]  = {p4.x, p4.y, p4.z, p4.w};
            float qv[4]  = {q4.x, q4.y, q4.z, q4.w};
#pragma unroll
            for (int i = 0; i < 4; i++)
#pragma unroll
                for (int j = 0; j < 4; j++) {
                    acc1[i][j] += a1v[i] * pv[j];
                    acc2[i][j] += a2v[i] * qv[j];
                }
        }
        __syncthreads();
    }
#pragma unroll
    for (int i = 0; i < 4; i++) {
        int m = bm + ty * 4 + i;
#pragma unroll
        for (int j = 0; j < 4; j++) {
            int n = bn + tx * 4 + j;
            g_emb[m * DH + n] = lrelu(acc1[i][j] + b1[n]) + lrelu(acc2[i][j] + b2[n]);
        }
    }
}

// ---------------- K7: node scores a = lrelu(emb@att1+b)@att2+b -------------
__global__ void k7_readout(const float* __restrict__ att1_w, const float* __restrict__ att1_b,
                           const float* __restrict__ att2_w, const float* __restrict__ att2_b) {
    __shared__ float se[K7NODES][DH];
    __shared__ float warpred[8];
    int n0 = blockIdx.x * K7NODES;
    int tid = threadIdx.x;
    for (int i = tid; i < K7NODES * DH; i += 256)
        se[i >> 9][i & 511] = g_emb[(n0 + (i >> 9)) * DH + (i & 511)];
    __syncthreads();

    int j = tid;
    float acc[K7NODES];
#pragma unroll
    for (int m = 0; m < K7NODES; m++) acc[m] = 0.0f;

    for (int d = 0; d < DH; d += 4) {
        float w0 = att1_w[(d + 0) * DH2 + j];
        float w1 = att1_w[(d + 1) * DH2 + j];
        float w2 = att1_w[(d + 2) * DH2 + j];
        float w3 = att1_w[(d + 3) * DH2 + j];
#pragma unroll
        for (int m = 0; m < K7NODES; m++) {
            float4 e = *(const float4*)&se[m][d];
            acc[m] += e.x * w0 + e.y * w1 + e.z * w2 + e.w * w3;
        }
    }
    float b1 = att1_b[j], a2 = att2_w[j], b2v = att2_b[0];
    int lane = tid & 31, wid = tid >> 5;
    for (int m = 0; m < K7NODES; m++) {
        float v = lrelu(acc[m] + b1) * a2;
#pragma unroll
        for (int o = 16; o > 0; o >>= 1) v += __shfl_xor_sync(0xffffffffu, v, o);
        if (lane == 0) warpred[wid] = v;
        __syncthreads();
        if (tid == 0) {
            float s = 0.0f;
            for (int q = 0; q < 8; q++) s += warpred[q];
            g_a[n0 + m] = s + b2v;
        }
        __syncthreads();
    }
}

// ---------------- K8: softmax over nodes -----------------------------------
__global__ void k8_softmax() {
    __shared__ float red[1024];
    int tid = threadIdx.x;
    float lm = -FLT_MAX;
    for (int i = tid; i < NN; i += 1024) lm = fmaxf(lm, g_a[i]);
    red[tid] = lm;
    __syncthreads();
    for (int s = 512; s > 0; s >>= 1) {
        if (tid < s) red[tid] = fmaxf(red[tid], red[tid + s]);
        __syncthreads();
    }
    float amax = red[0];
    __syncthreads();
    float ls = 0.0f;
    for (int i = tid; i < NN; i += 1024) {
        float w = expf(g_a[i] - amax);
        g_a[i] = w;
        ls += w;
    }
    red[tid] = ls;
    __syncthreads();
    for (int s = 512; s > 0; s >>= 1) {
        if (tid < s) red[tid] += red[tid + s];
        __syncthreads();
    }
    if (tid == 0) g_Z[0] = red[0];
}

// ---------------- K9: partial weighted sums over nodes ---------------------
__global__ void k9_wsum() {
    int d = blockIdx.x * 128 + threadIdx.x;
    int r0 = blockIdx.y * 256;
    float s = 0.0f;
    for (int i = 0; i < 256; i++) s += g_a[r0 + i] * g_emb[(r0 + i) * DH + d];
    g_part2[blockIdx.y * DH + d] = s;
}

// ---------------- K10: finalize: h, layernorm, logits ----------------------
__global__ void k10_final(const float* __restrict__ ln_g, const float* __restrict__ ln_b,
                          const float* __restrict__ fc_w, const float* __restrict__ fc_b,
                          float* __restrict__ out) {
    __shared__ float red[DH];
    int tid = threadIdx.x;
    float raw = 0.0f;
    for (int p = 0; p < 32; p++) raw += g_part2[p * DH + tid];
    float h = raw / g_Z[0];

    red[tid] = h;
    __syncthreads();
    for (int s = 256; s > 0; s >>= 1) {
        if (tid < s) red[tid] += red[tid + s];
        __syncthreads();
    }
    float mu = red[0] * (1.0f / DH);
    __syncthreads();
    float dv = h - mu;
    red[tid] = dv * dv;
    __syncthreads();
    for (int s = 256; s > 0; s >>= 1) {
        if (tid < s) red[tid] += red[tid + s];
        __syncthreads();
    }
    float var = red[0] * (1.0f / DH);
    __syncthreads();
    float hn = dv * rsqrtf(var + 1e-5f) * ln_g[tid] + ln_b[tid];

    float p0 = hn * fc_w[tid * 2 + 0];
    float p1 = hn * fc_w[tid * 2 + 1];
    red[tid] = p0;
    __syncthreads();
    for (int s = 256; s > 0; s >>= 1) {
        if (tid < s) red[tid] += red[tid + s];
        __syncthreads();
    }
    float s0 = red[0];
    __syncthreads();
    red[tid] = p1;
    __syncthreads();
    for (int s = 256; s > 0; s >>= 1) {
        if (tid < s) red[tid] += red[tid + s];
        __syncthreads();
    }
    if (tid == 0) {
        out[0] = s0 + fc_b[0];
        out[1] = red[0] + fc_b[1];
    }
}

// ---------------- launch ---------------------------------------------------
extern "C" void kernel_launch(void* const* d_in, const int* in_sizes, int n_in,
                              void* d_out, int out_size) {
    (void)in_sizes; (void)n_in; (void)out_size;
    const float* x_s    = (const float*)d_in[0];
    const float* fc1_w  = (const float*)d_in[1];
    const float* fc1_b  = (const float*)d_in[2];
    const float* wh_w   = (const float*)d_in[3];
    const float* wh_b   = (const float*)d_in[4];
    const float* wt_w   = (const float*)d_in[5];
    const float* wt_b   = (const float*)d_in[6];
    const float* l1_w   = (const float*)d_in[7];
    const float* l1_b   = (const float*)d_in[8];
    const float* l2_w   = (const float*)d_in[9];
    const float* l2_b   = (const float*)d_in[10];
    const float* att1_w = (const float*)d_in[11];
    const float* att1_b = (const float*)d_in[12];
    const float* att2_w = (const float*)d_in[13];
    const float* att2_b = (const float*)d_in[14];
    const float* ln_g   = (const float*)d_in[15];
    const float* ln_b   = (const float*)d_in[16];
    const float* fc_w   = (const float*)d_in[17];
    const float* fc_b   = (const float*)d_in[18];
    float* out = (float*)d_out;

    static int smem_set = 0;
    if (!smem_set) {
        cudaFuncSetAttribute(k4_tc, cudaFuncAttributeMaxDynamicSharedMemorySize,
                             SMEM4_TOTAL);
        smem_set = 1;
    }

    dim3 gg(DH / 64, NN / 64);
    k1_fc1<<<gg, 256>>>(x_s, fc1_w, fc1_b);
    k2_colpart<<<dim3(2, 32), 256>>>();
    k2b_colmean<<<1, DH>>>();
    k3_dual<<<gg, 256>>>(wh_w, wh_b, wt_w, wt_b);
    k4_tc<<<NN / 64, 256, SMEM4_TOTAL>>>();
    k4b_refine<<<NN / 8, 256>>>();
    k5_neigh<<<NN / 8, 256>>>();
    k6_dual<<<gg, 256>>>(l1_w, l1_b, l2_w, l2_b);
    k7_readout<<<NN / K7NODES, 256>>>(att1_w, att1_b, att2_w, att2_b);
    k8_softmax<<<1, 1024>>>();
    k9_wsum<<<dim3(4, 32), 128>>>();
    k10_final<<<1, DH>>>(ln_g, ln_b, fc_w, fc_b, out);
}

// round 3
// speedup vs baseline: 6.1097x; 1.5806x over previous
#include <cuda_runtime.h>
#include <cuda_bf16.h>
#include <math.h>
#include <float.h>
#include <stdint.h>

#define NN   8192
#define DIN  384
#define DH   512
#define KTOP 6
#define DH2  256
#define K7NODES 16
#define NCAND 24
#define BST  72   // smem k/n stride (bf16 elems) for weight GEMMs

// ---------------- scratch (static device globals; no runtime allocation) ---
__device__ float g_x[NN * DH];
__device__ float g_eh[NN * DH];
__device__ float g_et[NN * DH];
__device__ __nv_bfloat16 g_ehb[NN * DH];
__device__ __nv_bfloat16 g_etb[NN * DH];
__device__ float g_s1[NN * DH];
__device__ float g_s2[NN * DH];
__device__ float g_emb[NN * DH];
__device__ float g_mean[DH];
__device__ float g_part1[32 * DH];
__device__ float g_part2[32 * DH];
__device__ float g_topkw[NN * KTOP];
__device__ int   g_topki[NN * KTOP];
__device__ int   g_candi[NN * NCAND];
__device__ float g_a[NN];
__device__ float g_Z[1];

__device__ __forceinline__ float lrelu(float v) { return v > 0.0f ? v : 0.01f * v; }

__device__ __forceinline__ float tanh_fast(float x) {
    float y;
    asm("tanh.approx.f32 %0, %1;" : "=f"(y) : "f"(x));
    return y;
}

__device__ __forceinline__ uint32_t saddr(const void* p) {
    return (uint32_t)__cvta_generic_to_shared(p);
}

__device__ __forceinline__ void ldsm4(unsigned r[4], uint32_t addr) {
    asm volatile("ldmatrix.sync.aligned.m8n8.x4.shared.b16 {%0,%1,%2,%3}, [%4];"
                 : "=r"(r[0]), "=r"(r[1]), "=r"(r[2]), "=r"(r[3]) : "r"(addr));
}

__device__ __forceinline__ void ldsm4t(unsigned r[4], uint32_t addr) {
    asm volatile("ldmatrix.sync.aligned.m8n8.x4.trans.shared.b16 {%0,%1,%2,%3}, [%4];"
                 : "=r"(r[0]), "=r"(r[1]), "=r"(r[2]), "=r"(r[3]) : "r"(addr));
}

__device__ __forceinline__ void mma_bf16(float* d, const unsigned a[4],
                                         unsigned b0, unsigned b1) {
    asm volatile("mma.sync.aligned.m16n8k16.row.col.f32.bf16.bf16.f32 "
                 "{%0,%1,%2,%3}, {%4,%5,%6,%7}, {%8,%9}, {%0,%1,%2,%3};"
                 : "+f"(d[0]), "+f"(d[1]), "+f"(d[2]), "+f"(d[3])
                 : "r"(a[0]), "r"(a[1]), "r"(a[2]), "r"(a[3]), "r"(b0), "r"(b1));
}

__device__ __forceinline__ void cpa16(uint32_t s, const void* g) {
    asm volatile("cp.async.cg.shared.global [%0], [%1], 16;" :: "r"(s), "l"(g));
}
__device__ __forceinline__ void cpa_commit() {
    asm volatile("cp.async.commit_group;");
}

// split fp32 float4 into hi/lo bf16 pairs stored to smem
__device__ __forceinline__ void split4(float4 v, __nv_bfloat16* hi, __nv_bfloat16* lo) {
    __nv_bfloat16 h0 = __float2bfloat16(v.x), h1 = __float2bfloat16(v.y);
    __nv_bfloat16 h2 = __float2bfloat16(v.z), h3 = __float2bfloat16(v.w);
    __nv_bfloat16 l0 = __float2bfloat16(v.x - __bfloat162float(h0));
    __nv_bfloat16 l1 = __float2bfloat16(v.y - __bfloat162float(h1));
    __nv_bfloat16 l2 = __float2bfloat16(v.z - __bfloat162float(h2));
    __nv_bfloat16 l3 = __float2bfloat16(v.w - __bfloat162float(h3));
    *(__nv_bfloat162*)(hi)     = __halves2bfloat162(h0, h1);
    *(__nv_bfloat162*)(hi + 2) = __halves2bfloat162(h2, h3);
    *(__nv_bfloat162*)(lo)     = __halves2bfloat162(l0, l1);
    *(__nv_bfloat162*)(lo + 2) = __halves2bfloat162(l2, l3);
}

// ---------------- K1: x = lrelu(x_s @ fc1_w + fc1_b)  (split-bf16 TC) ------
__global__ void __launch_bounds__(256) k1_tc(const float* __restrict__ A,
                                             const float* __restrict__ B,
                                             const float* __restrict__ bias) {
    __shared__ __nv_bfloat16 Ah[64 * BST], Al[64 * BST];
    __shared__ __nv_bfloat16 Bh[64 * BST], Bl[64 * BST];
    int bm = blockIdx.y * 64, bn = blockIdx.x * 64;
    int tid = threadIdx.x, warp = tid >> 5, lane = tid & 31;
    int wm = warp & 1, wn = warp >> 1;
    int lrow = lane & 15, lkoff = (lane >> 4) * 8;
    float acc[2][2][4] = {};
    for (int k0 = 0; k0 < DIN; k0 += 64) {
        __syncthreads();
        for (int it = tid; it < 1024; it += 256) {
            int row = it >> 4, c4 = (it & 15) * 4;
            float4 v = *(const float4*)&A[(size_t)(bm + row) * DIN + k0 + c4];
            split4(v, Ah + row * BST + c4, Al + row * BST + c4);
        }
        for (int it = tid; it < 1024; it += 256) {
            int row = it >> 4, c4 = (it & 15) * 4;
            float4 v = *(const float4*)&B[(size_t)(k0 + row) * DH + bn + c4];
            split4(v, Bh + row * BST + c4, Bl + row * BST + c4);
        }
        __syncthreads();
#pragma unroll
        for (int ks = 0; ks < 4; ks++) {
            unsigned ah[2][4], al[2][4], ph[4], pl[4];
            ldsm4(ah[0], saddr(&Ah[(wm * 32 + lrow) * BST + ks * 16 + lkoff]));
            ldsm4(ah[1], saddr(&Ah[(wm * 32 + 16 + lrow) * BST + ks * 16 + lkoff]));
            ldsm4(al[0], saddr(&Al[(wm * 32 + lrow) * BST + ks * 16 + lkoff]));
            ldsm4(al[1], saddr(&Al[(wm * 32 + 16 + lrow) * BST + ks * 16 + lkoff]));
            int boff = (ks * 16 + (lane & 7) + 8 * ((lane >> 3) & 1)) * BST +
                       wn * 16 + 8 * (lane >> 4);
            ldsm4t(ph, saddr(&Bh[boff]));
            ldsm4t(pl, saddr(&Bl[boff]));
#pragma unroll
            for (int m = 0; m < 2; m++)
#pragma unroll
                for (int n = 0; n < 2; n++) {
                    mma_bf16(acc[m][n], ah[m], ph[n * 2], ph[n * 2 + 1]);
                    mma_bf16(acc[m][n], ah[m], pl[n * 2], pl[n * 2 + 1]);
                    mma_bf16(acc[m][n], al[m], ph[n * 2], ph[n * 2 + 1]);
                }
        }
    }
#pragma unroll
    for (int m = 0; m < 2; m++)
#pragma unroll
        for (int n = 0; n < 2; n++) {
            int row = bm + wm * 32 + m * 16 + (lane >> 2);
            int col = bn + wn * 16 + n * 8 + (lane & 3) * 2;
            g_x[(size_t)row * DH + col]           = lrelu(acc[m][n][0] + bias[col]);
            g_x[(size_t)row * DH + col + 1]       = lrelu(acc[m][n][1] + bias[col + 1]);
            g_x[(size_t)(row + 8) * DH + col]     = lrelu(acc[m][n][2] + bias[col]);
            g_x[(size_t)(row + 8) * DH + col + 1] = lrelu(acc[m][n][3] + bias[col + 1]);
        }
}

// ---------------- K2: column mean of x (deterministic two-stage) ----------
__global__ void k2_colpart() {
    int c = blockIdx.x * 256 + threadIdx.x;
    int r0 = blockIdx.y * 256;
    float s = 0.0f;
    for (int i = 0; i < 256; i++) s += g_x[(r0 + i) * DH + c];
    g_part1[blockIdx.y * DH + c] = s;
}

__global__ void k2b_colmean() {
    int c = threadIdx.x;
    float s = 0.0f;
    for (int p = 0; p < 32; p++) s += g_part1[p * DH + c];
    g_mean[c] = s * (1.0f / NN);
}

// ---------------- K3: e_h / e_t dual GEMM (split-bf16 TC) ------------------
#define K3_SMEM (6 * 64 * BST * 2)
__global__ void __launch_bounds__(256) k3_tc(const float* __restrict__ B1,
                                             const float* __restrict__ b1,
                                             const float* __restrict__ B2,
                                             const float* __restrict__ b2) {
    extern __shared__ char sm3[];
    __nv_bfloat16* Ah  = (__nv_bfloat16*)(sm3);
    __nv_bfloat16* Al  = (__nv_bfloat16*)(sm3 + 1 * 9216);
    __nv_bfloat16* B1h = (__nv_bfloat16*)(sm3 + 2 * 9216);
    __nv_bfloat16* B1l = (__nv_bfloat16*)(sm3 + 3 * 9216);
    __nv_bfloat16* B2h = (__nv_bfloat16*)(sm3 + 4 * 9216);
    __nv_bfloat16* B2l = (__nv_bfloat16*)(sm3 + 5 * 9216);
    int bm = blockIdx.y * 64, bn = blockIdx.x * 64;
    int tid = threadIdx.x, warp = tid >> 5, lane = tid & 31;
    int wm = warp & 1, wn = warp >> 1;
    int lrow = lane & 15, lkoff = (lane >> 4) * 8;
    float acc1[2][2][4] = {}, acc2[2][2][4] = {};
    for (int k0 = 0; k0 < DH; k0 += 64) {
        __syncthreads();
        for (int it = tid; it < 1024; it += 256) {
            int row = it >> 4, c4 = (it & 15) * 4;
            float4 v = *(const float4*)&g_x[(size_t)(bm + row) * DH + k0 + c4];
            float4 mu = *(const float4*)&g_mean[k0 + c4];
            v.x = (v.x + mu.x) * 0.5f; v.y = (v.y + mu.y) * 0.5f;
            v.z = (v.z + mu.z) * 0.5f; v.w = (v.w + mu.w) * 0.5f;
            split4(v, Ah + row * BST + c4, Al + row * BST + c4);
        }
        for (int it = tid; it < 1024; it += 256) {
            int row = it >> 4, c4 = (it & 15) * 4;
            float4 v = *(const float4*)&B1[(size_t)(k0 + row) * DH + bn + c4];
            split4(v, B1h + row * BST + c4, B1l + row * BST + c4);
            float4 w = *(const float4*)&B2[(size_t)(k0 + row) * DH + bn + c4];
            split4(w, B2h + row * BST + c4, B2l + row * BST + c4);
        }
        __syncthreads();
#pragma unroll
        for (int ks = 0; ks < 4; ks++) {
            unsigned ah[2][4], al[2][4];
            ldsm4(ah[0], saddr(&Ah[(wm * 32 + lrow) * BST + ks * 16 + lkoff]));
            ldsm4(ah[1], saddr(&Ah[(wm * 32 + 16 + lrow) * BST + ks * 16 + lkoff]));
            ldsm4(al[0], saddr(&Al[(wm * 32 + lrow) * BST + ks * 16 + lkoff]));
            ldsm4(al[1], saddr(&Al[(wm * 32 + 16 + lrow) * BST + ks * 16 + lkoff]));
            int boff = (ks * 16 + (lane & 7) + 8 * ((lane >> 3) & 1)) * BST +
                       wn * 16 + 8 * (lane >> 4);
            unsigned p1h[4], p1l[4], p2h[4], p2l[4];
            ldsm4t(p1h, saddr(&B1h[boff]));
            ldsm4t(p1l, saddr(&B1l[boff]));
            ldsm4t(p2h, saddr(&B2h[boff]));
            ldsm4t(p2l, saddr(&B2l[boff]));
#pragma unroll
            for (int m = 0; m < 2; m++)
#pragma unroll
                for (int n = 0; n < 2; n++) {
                    mma_bf16(acc1[m][n], ah[m], p1h[n * 2], p1h[n * 2 + 1]);
                    mma_bf16(acc1[m][n], ah[m], p1l[n * 2], p1l[n * 2 + 1]);
                    mma_bf16(acc1[m][n], al[m], p1h[n * 2], p1h[n * 2 + 1]);
                    mma_bf16(acc2[m][n], ah[m], p2h[n * 2], p2h[n * 2 + 1]);
                    mma_bf16(acc2[m][n], ah[m], p2l[n * 2], p2l[n * 2 + 1]);
                    mma_bf16(acc2[m][n], al[m], p2h[n * 2], p2h[n * 2 + 1]);
                }
        }
    }
#pragma unroll
    for (int m = 0; m < 2; m++)
#pragma unroll
        for (int n = 0; n < 2; n++) {
            int row = bm + wm * 32 + m * 16 + (lane >> 2);
            int col = bn + wn * 16 + n * 8 + (lane & 3) * 2;
            float v0 = acc1[m][n][0] + b1[col], v1 = acc1[m][n][1] + b1[col + 1];
            float v2 = acc1[m][n][2] + b1[col], v3 = acc1[m][n][3] + b1[col + 1];
            g_eh[(size_t)row * DH + col] = v0;       g_eh[(size_t)row * DH + col + 1] = v1;
            g_eh[(size_t)(row + 8) * DH + col] = v2; g_eh[(size_t)(row + 8) * DH + col + 1] = v3;
            g_ehb[(size_t)row * DH + col] = __float2bfloat16(v0);
            g_ehb[(size_t)row * DH + col + 1] = __float2bfloat16(v1);
            g_ehb[(size_t)(row + 8) * DH + col] = __float2bfloat16(v2);
            g_ehb[(size_t)(row + 8) * DH + col + 1] = __float2bfloat16(v3);
            float w0 = acc2[m][n][0] + b2[col], w1 = acc2[m][n][1] + b2[col + 1];
            float w2 = acc2[m][n][2] + b2[col], w3 = acc2[m][n][3] + b2[col + 1];
            g_et[(size_t)row * DH + col] = w0;       g_et[(size_t)row * DH + col + 1] = w1;
            g_et[(size_t)(row + 8) * DH + col] = w2; g_et[(size_t)(row + 8) * DH + col + 1] = w3;
            g_etb[(size_t)row * DH + col] = __float2bfloat16(w0);
            g_etb[(size_t)row * DH + col + 1] = __float2bfloat16(w1);
            g_etb[(size_t)(row + 8) * DH + col] = __float2bfloat16(w2);
            g_etb[(size_t)(row + 8) * DH + col + 1] = __float2bfloat16(w3);
        }
}

// ---------------- K4: tensor-core score GEMM + candidate top-6 -------------
// 64 rows per block; A stripe resident; B streamed in 128x128 bf16 chunks via
// double-buffered cp.async. 4 threads/row keep quarter top-6 -> 24 candidates.
#define ASTRIDE 520
#define B4STRIDE 136
#define SSTRIDE 132
#define SMEM_A_BYTES (64 * ASTRIDE * 2)               // 66560
#define B4_CHUNK_BYTES (128 * B4STRIDE * 2)           // 34816
#define SMEM_B_BYTES (2 * B4_CHUNK_BYTES)             // 69632
#define SMEM_S_BYTES (64 * SSTRIDE * 4)               // 33792
#define SMEM4_TOTAL (SMEM_A_BYTES + SMEM_B_BYTES + SMEM_S_BYTES)

__global__ void __launch_bounds__(256, 1) k4_tc() {
    extern __shared__ char sm4[];
    __nv_bfloat16* As = (__nv_bfloat16*)sm4;
    __nv_bfloat16* Bs0 = (__nv_bfloat16*)(sm4 + SMEM_A_BYTES);
    __nv_bfloat16* Bs1 = (__nv_bfloat16*)(sm4 + SMEM_A_BYTES + B4_CHUNK_BYTES);
    float* Ssc = (float*)(sm4 + SMEM_A_BYTES + SMEM_B_BYTES);

    int tid = threadIdx.x;
    int warp = tid >> 5, lane = tid & 31;
    int wm = warp & 1, wn = warp >> 1;
    int bm = blockIdx.x * 64;
    int lrow = lane & 15, lkoff = (lane >> 4) * 8;
    int myrow = tid >> 2, myq = tid & 3;

    int ldrow = tid >> 1, ldseg = (tid & 1) * 64;
    uint32_t b0addr = saddr(Bs0) + (ldrow * B4STRIDE + ldseg) * 2;
    uint32_t b1addr = saddr(Bs1) + (ldrow * B4STRIDE + ldseg) * 2;

    // issue chunk 0
    {
        const __nv_bfloat16* src = g_etb + (size_t)ldrow * DH + ldseg;
#pragma unroll
        for (int j = 0; j < 8; j++) cpa16(b0addr + j * 16, src + j * 8);
        cpa_commit();
    }

    // Load A stripe (64 x 512) once.
    for (int i = tid; i < 64 * 64; i += 256) {
        int row = i >> 6, c4 = i & 63;
        *(uint4*)(As + row * ASTRIDE + c4 * 8) =
            *(const uint4*)(g_ehb + (size_t)(bm + row) * DH + c4 * 8);
    }

    float tv[KTOP];
    int ti[KTOP];
#pragma unroll
    for (int k = 0; k < KTOP; k++) { tv[k] = -FLT_MAX; ti[k] = 0; }

    const float scale = 0.044194173824159216f;

    for (int tile = 0; tile < 64; tile++) {
        float acc[2][4][4];
#pragma unroll
        for (int a = 0; a < 2; a++)
#pragma unroll
            for (int b = 0; b < 4; b++)
#pragma unroll
                for (int c = 0; c < 4; c++) acc[a][b][c] = 0.0f;

        for (int ch = 0; ch < 4; ch++) {
            int q = tile * 4 + ch;
            if (q + 1 < 256) {
                int nq = q + 1;
                int ntile = nq >> 2, nch = nq & 3;
                const __nv_bfloat16* src =
                    g_etb + (size_t)(ntile * 128 + ldrow) * DH + nch * 128 + ldseg;
                uint32_t dst = (nq & 1) ? b1addr : b0addr;
#pragma unroll
                for (int j = 0; j < 8; j++) cpa16(dst + j * 16, src + j * 8);
                cpa_commit();
                asm volatile("cp.async.wait_group 1;");
            } else {
                asm volatile("cp.async.wait_group 0;");
            }
            __syncthreads();
            __nv_bfloat16* Bs = (q & 1) ? Bs1 : Bs0;
#pragma unroll
            for (int ks = 0; ks < 8; ks++) {
                unsigned a0[4], a1[4], b0[4], b1[4];
                int kA = ch * 128 + ks * 16 + lkoff;
                ldsm4(a0, saddr(&As[(wm * 32 + lrow) * ASTRIDE + kA]));
                ldsm4(a1, saddr(&As[(wm * 32 + 16 + lrow) * ASTRIDE + kA]));
                int kB = ks * 16 + lkoff;
                ldsm4(b0, saddr(&Bs[(wn * 32 + lrow) * B4STRIDE + kB]));
                ldsm4(b1, saddr(&Bs[(wn * 32 + 16 + lrow) * B4STRIDE + kB]));
                mma_bf16(acc[0][0], a0, b0[0], b0[2]);
                mma_bf16(acc[0][1], a0, b0[1], b0[3]);
                mma_bf16(acc[0][2], a0, b1[0], b1[2]);
                mma_bf16(acc[0][3], a0, b1[1], b1[3]);
                mma_bf16(acc[1][0], a1, b0[0], b0[2]);
                mma_bf16(acc[1][1], a1, b0[1], b0[3]);
                mma_bf16(acc[1][2], a1, b1[0], b1[2]);
                mma_bf16(acc[1][3], a1, b1[1], b1[3]);
            }
            __syncthreads();
        }
        int g = lane >> 2, tg = lane & 3;
#pragma unroll
        for (int msub = 0; msub < 2; msub++) {
            int row0 = wm * 32 + msub * 16 + g;
#pragma unroll
            for (int nsub = 0; nsub < 4; nsub++) {
                int col = wn * 32 + nsub * 8 + tg * 2;
                Ssc[row0 * SSTRIDE + col]           = acc[msub][nsub][0];
                Ssc[row0 * SSTRIDE + col + 1]       = acc[msub][nsub][1];
                Ssc[(row0 + 8) * SSTRIDE + col]     = acc[msub][nsub][2];
                Ssc[(row0 + 8) * SSTRIDE + col + 1] = acc[msub][nsub][3];
            }
        }
        __syncthreads();
        int bn = tile * 128;
#pragma unroll 1
        for (int j = 0; j < 32; j++) {
            float v = Ssc[myrow * SSTRIDE + myq * 32 + j] * scale;
            if (v > tv[KTOP - 1]) {
                tv[KTOP - 1] = v;
                ti[KTOP - 1] = bn + myq * 32 + j;
#pragma unroll
                for (int p = KTOP - 1; p > 0; p--) {
                    if (tv[p] > tv[p - 1]) {
                        float tf = tv[p]; tv[p] = tv[p - 1]; tv[p - 1] = tf;
                        int tt = ti[p]; ti[p] = ti[p - 1]; ti[p - 1] = tt;
                    }
                }
            }
        }
        __syncthreads();
    }
#pragma unroll
    for (int k = 0; k < KTOP; k++)
        g_candi[(size_t)(bm + myrow) * NCAND + myq * KTOP + k] = ti[k];
}

// ---------------- K4b: exact fp32 refinement of 24 candidates -> top-6 -----
__global__ void __launch_bounds__(256) k4b_refine() {
    int node = blockIdx.x * 8 + (threadIdx.x >> 5);
    int lane = threadIdx.x & 31;
    const float scale = 0.044194173824159216f;

    float eh[16];
#pragma unroll
    for (int t = 0; t < 16; t++) eh[t] = g_eh[(size_t)node * DH + lane + t * 32];

    float vals[NCAND];
    int idxs[NCAND];
#pragma unroll
    for (int c = 0; c < NCAND; c++) {
        int idx = g_candi[(size_t)node * NCAND + c];
        idxs[c] = idx;
        const float* et = g_et + (size_t)idx * DH;
        float s = 0.0f;
#pragma unroll
        for (int t = 0; t < 16; t++) s += eh[t] * et[lane + t * 32];
#pragma unroll
        for (int o = 16; o > 0; o >>= 1) s += __shfl_xor_sync(0xffffffffu, s, o);
        vals[c] = s * scale;
    }

    unsigned used = 0;
#pragma unroll
    for (int p = 0; p < KTOP; p++) {
        float bv = -FLT_MAX; int bi = 0x7fffffff; int bc = 0;
#pragma unroll
        for (int c = 0; c < NCAND; c++) {
            if (!((used >> c) & 1u)) {
                if (vals[c] > bv || (vals[c] == bv && idxs[c] < bi)) {
                    bv = vals[c]; bi = idxs[c]; bc = c;
                }
            }
        }
        used |= 1u << bc;
        if (lane == 0) {
            g_topkw[node * KTOP + p] = bv;
            g_topki[node * KTOP + p] = bi;
        }
    }
}

// ---------------- K5: per-node neighbor aggregation -> s1, s2 --------------
__global__ void __launch_bounds__(256) k5_neigh() {
    int node = (blockIdx.x * 256 + threadIdx.x) >> 5;
    int lane = threadIdx.x & 31;
    if (node >= NN) return;

    float w[KTOP];
    int idx[KTOP];
#pragma unroll
    for (int k = 0; k < KTOP; k++) {
        w[k] = g_topkw[node * KTOP + k];
        idx[k] = g_topki[node * KTOP + k];
    }
    float p[KTOP], ps = 0.0f;
#pragma unroll
    for (int k = 0; k < KTOP; k++) { p[k] = __expf(w[k] - w[0]); ps += p[k]; }
    float pinv = 1.0f / ps;
#pragma unroll
    for (int k = 0; k < KTOP; k++) p[k] *= pinv;

    float ehv[16], nb[KTOP][16];
#pragma unroll
    for (int t = 0; t < 16; t++) ehv[t] = g_eh[node * DH + lane + t * 32];
#pragma unroll
    for (int k = 0; k < KTOP; k++)
#pragma unroll
        for (int t = 0; t < 16; t++)
            nb[k][t] = g_et[idx[k] * DH + lane + t * 32];

    float ka[KTOP];
#pragma unroll
    for (int k = 0; k < KTOP; k++) {
        float s = 0.0f;
#pragma unroll
        for (int t = 0; t < 16; t++) {
            float ehr  = p[k] * nb[k][t] + (1.0f - p[k]) * ehv[t];
            float gate = tanh_fast(ehv[t] + ehr);
            s += nb[k][t] * gate;
        }
#pragma unroll
        for (int o = 16; o > 0; o >>= 1) s += __shfl_xor_sync(0xffffffffu, s, o);
        ka[k] = s;
    }
    float km = ka[0];
#pragma unroll
    for (int k = 1; k < KTOP; k++) km = fmaxf(km, ka[k]);
    float kp[KTOP], ks = 0.0f;
#pragma unroll
    for (int k = 0; k < KTOP; k++) { kp[k] = __expf(ka[k] - km); ks += kp[k]; }
    float kinv = 1.0f / ks;
#pragma unroll
    for (int k = 0; k < KTOP; k++) kp[k] *= kinv;

#pragma unroll
    for (int t = 0; t < 16; t++) {
        float enh = 0.0f;
#pragma unroll
        for (int k = 0; k < KTOP; k++) enh += kp[k] * nb[k][t];
        int d = lane + t * 32;
        g_s1[node * DH + d] = ehv[t] + enh;
        g_s2[node * DH + d] = ehv[t] * enh;
    }
}

// ---------------- K6: emb = lrelu(s1@l1+b1)+lrelu(s2@l2+b2)  (TC) ----------
#define K6_SMEM (8 * 64 * BST * 2)
__global__ void __launch_bounds__(256) k6_tc(const float* __restrict__ B1,
                                             const float* __restrict__ b1,
                                             const float* __restrict__ B2,
                                             const float* __restrict__ b2) {
    extern __shared__ char sm6[];
    __nv_bfloat16* A1h = (__nv_bfloat16*)(sm6);
    __nv_bfloat16* A1l = (__nv_bfloat16*)(sm6 + 1 * 9216);
    __nv_bfloat16* A2h = (__nv_bfloat16*)(sm6 + 2 * 9216);
    __nv_bfloat16* A2l = (__nv_bfloat16*)(sm6 + 3 * 9216);
    __nv_bfloat16* B1h = (__nv_bfloat16*)(sm6 + 4 * 9216);
    __nv_bfloat16* B1l = (__nv_bfloat16*)(sm6 + 5 * 9216);
    __nv_bfloat16* B2h = (__nv_bfloat16*)(sm6 + 6 * 9216);
    __nv_bfloat16* B2l = (__nv_bfloat16*)(sm6 + 7 * 9216);
    int bm = blockIdx.y * 64, bn = blockIdx.x * 64;
    int tid = threadIdx.x, warp = tid >> 5, lane = tid & 31;
    int wm = warp & 1, wn = warp >> 1;
    int lrow = lane & 15, lkoff = (lane >> 4) * 8;
    float acc1[2][2][4] = {}, acc2[2][2][4] = {};
    for (int k0 = 0; k0 < DH; k0 += 64) {
        __syncthreads();
        for (int it = tid; it < 1024; it += 256) {
            int row = it >> 4, c4 = (it & 15) * 4;
            float4 v = *(const float4*)&g_s1[(size_t)(bm + row) * DH + k0 + c4];
            split4(v, A1h + row * BST + c4, A1l + row * BST + c4);
            float4 w = *(const float4*)&g_s2[(size_t)(bm + row) * DH + k0 + c4];
            split4(w, A2h + row * BST + c4, A2l + row * BST + c4);
        }
        for (int it = tid; it < 1024; it += 256) {
            int row = it >> 4, c4 = (it & 15) * 4;
            float4 v = *(const float4*)&B1[(size_t)(k0 + row) * DH + bn + c4];
            split4(v, B1h + row * BST + c4, B1l + row * BST + c4);
            float4 w = *(const float4*)&B2[(size_t)(k0 + row) * DH + bn + c4];
            split4(w, B2h + row * BST + c4, B2l + row * BST + c4);
        }
        __syncthreads();
#pragma unroll
        for (int ks = 0; ks < 4; ks++) {
            unsigned a1h[2][4], a1l[2][4], a2h[2][4], a2l[2][4];
            ldsm4(a1h[0], saddr(&A1h[(wm * 32 + lrow) * BST + ks * 16 + lkoff]));
            ldsm4(a1h[1], saddr(&A1h[(wm * 32 + 16 + lrow) * BST + ks * 16 + lkoff]));
            ldsm4(a1l[0], saddr(&A1l[(wm * 32 + lrow) * BST + ks * 16 + lkoff]));
            ldsm4(a1l[1], saddr(&A1l[(wm * 32 + 16 + lrow) * BST + ks * 16 + lkoff]));
            ldsm4(a2h[0], saddr(&A2h[(wm * 32 + lrow) * BST + ks * 16 + lkoff]));
            ldsm4(a2h[1], saddr(&A2h[(wm * 32 + 16 + lrow) * BST + ks * 16 + lkoff]));
            ldsm4(a2l[0], saddr(&A2l[(wm * 32 + lrow) * BST + ks * 16 + lkoff]));
            ldsm4(a2l[1], saddr(&A2l[(wm * 32 + 16 + lrow) * BST + ks * 16 + lkoff]));
            int boff = (ks * 16 + (lane & 7) + 8 * ((lane >> 3) & 1)) * BST +
                       wn * 16 + 8 * (lane >> 4);
            unsigned p1h[4], p1l[4], p2h[4], p2l[4];
            ldsm4t(p1h, saddr(&B1h[boff]));
            ldsm4t(p1l, saddr(&B1l[boff]));
            ldsm4t(p2h, saddr(&B2h[boff]));
            ldsm4t(p2l, saddr(&B2l[boff]));
#pragma unroll
            for (int m = 0; m < 2; m++)
#pragma unroll
                for (int n = 0; n < 2; n++) {
                    mma_bf16(acc1[m][n], a1h[m], p1h[n * 2], p1h[n * 2 + 1]);
                    mma_bf16(acc1[m][n], a1h[m], p1l[n * 2], p1l[n * 2 + 1]);
                    mma_bf16(acc1[m][n], a1l[m], p1h[n * 2], p1h[n * 2 + 1]);
                    mma_bf16(acc2[m][n], a2h[m], p2h[n * 2], p2h[n * 2 + 1]);
                    mma_bf16(acc2[m][n], a2h[m], p2l[n * 2], p2l[n * 2 + 1]);
                    mma_bf16(acc2[m][n], a2l[m], p2h[n * 2], p2h[n * 2 + 1]);
                }
        }
    }
#pragma unroll
    for (int m = 0; m < 2; m++)
#pragma unroll
        for (int n = 0; n < 2; n++) {
            int row = bm + wm * 32 + m * 16 + (lane >> 2);
            int col = bn + wn * 16 + n * 8 + (lane & 3) * 2;
            g_emb[(size_t)row * DH + col] =
                lrelu(acc1[m][n][0] + b1[col]) + lrelu(acc2[m][n][0] + b2[col]);
            g_emb[(size_t)row * DH + col + 1] =
                lrelu(acc1[m][n][1] + b1[col + 1]) + lrelu(acc2[m][n][1] + b2[col + 1]);
            g_emb[(size_t)(row + 8) * DH + col] =
                lrelu(acc1[m][n][2] + b1[col]) + lrelu(acc2[m][n][2] + b2[col]);
            g_emb[(size_t)(row + 8) * DH + col + 1] =
                lrelu(acc1[m][n][3] + b1[col + 1]) + lrelu(acc2[m][n][3] + b2[col + 1]);
        }
}

// ---------------- K7: node scores a = lrelu(emb@att1+b)@att2+b -------------
__global__ void k7_readout(const float* __restrict__ att1_w, const float* __restrict__ att1_b,
                           const float* __restrict__ att2_w, const float* __restrict__ att2_b) {
    __shared__ float se[K7NODES][DH];
    __shared__ float warpred[8];
    int n0 = blockIdx.x * K7NODES;
    int tid = threadIdx.x;
    for (int i = tid; i < K7NODES * DH; i += 256)
        se[i >> 9][i & 511] = g_emb[(n0 + (i >> 9)) * DH + (i & 511)];
    __syncthreads();

    int j = tid;
    float acc[K7NODES];
#pragma unroll
    for (int m = 0; m < K7NODES; m++) acc[m] = 0.0f;

    for (int d = 0; d < DH; d += 4) {
        float w0 = att1_w[(d + 0) * DH2 + j];
        float w1 = att1_w[(d + 1) * DH2 + j];
        float w2 = att1_w[(d + 2) * DH2 + j];
        float w3 = att1_w[(d + 3) * DH2 + j];
#pragma unroll
        for (int m = 0; m < K7NODES; m++) {
            float4 e = *(const float4*)&se[m][d];
            acc[m] += e.x * w0 + e.y * w1 + e.z * w2 + e.w * w3;
        }
    }
    float b1 = att1_b[j], a2 = att2_w[j], b2v = att2_b[0];
    int lane = tid & 31, wid = tid >> 5;
    for (int m = 0; m < K7NODES; m++) {
        float v = lrelu(acc[m] + b1) * a2;
#pragma unroll
        for (int o = 16; o > 0; o >>= 1) v += __shfl_xor_sync(0xffffffffu, v, o);
        if (lane == 0) warpred[wid] = v;
        __syncthreads();
        if (tid == 0) {
            float s = 0.0f;
            for (int q = 0; q < 8; q++) s += warpred[q];
            g_a[n0 + m] = s + b2v;
        }
        __syncthreads();
    }
}

// ---------------- K8: softmax over nodes -----------------------------------
__global__ void k8_softmax() {
    __shared__ float red[1024];
    int tid = threadIdx.x;
    float lm = -FLT_MAX;
    for (int i = tid; i < NN; i += 1024) lm = fmaxf(lm, g_a[i]);
    red[tid] = lm;
    __syncthreads();
    for (int s = 512; s > 0; s >>= 1) {
        if (tid < s) red[tid] = fmaxf(red[tid], red[tid + s]);
        __syncthreads();
    }
    float amax = red[0];
    __syncthreads();
    float ls = 0.0f;
    for (int i = tid; i < NN; i += 1024) {
        float w = expf(g_a[i] - amax);
        g_a[i] = w;
        ls += w;
    }
    red[tid] = ls;
    __syncthreads();
    for (int s = 512; s > 0; s >>= 1) {
        if (tid < s) red[tid] += red[tid + s];
        __syncthreads();
    }
    if (tid == 0) g_Z[0] = red[0];
}

// ---------------- K9: partial weighted sums over nodes ---------------------
__global__ void k9_wsum() {
    int d = blockIdx.x * 128 + threadIdx.x;
    int r0 = blockIdx.y * 256;
    float s = 0.0f;
    for (int i = 0; i < 256; i++) s += g_a[r0 + i] * g_emb[(r0 + i) * DH + d];
    g_part2[blockIdx.y * DH + d] = s;
}

// ---------------- K10: finalize: h, layernorm, logits ----------------------
__global__ void k10_final(const float* __restrict__ ln_g, const float* __restrict__ ln_b,
                          const float* __restrict__ fc_w, const float* __restrict__ fc_b,
                          float* __restrict__ out) {
    __shared__ float red[DH];
    int tid = threadIdx.x;
    float raw = 0.0f;
    for (int p = 0; p < 32; p++) raw += g_part2[p * DH + tid];
    float h = raw / g_Z[0];

    red[tid] = h;
    __syncthreads();
    for (int s = 256; s > 0; s >>= 1) {
        if (tid < s) red[tid] += red[tid + s];
        __syncthreads();
    }
    float mu = red[0] * (1.0f / DH);
    __syncthreads();
    float dv = h - mu;
    red[tid] = dv * dv;
    __syncthreads();
    for (int s = 256; s > 0; s >>= 1) {
        if (tid < s) red[tid] += red[tid + s];
        __syncthreads();
    }
    float var = red[0] * (1.0f / DH);
    __syncthreads();
    float hn = dv * rsqrtf(var + 1e-5f) * ln_g[tid] + ln_b[tid];

    float p0 = hn * fc_w[tid * 2 + 0];
    float p1 = hn * fc_w[tid * 2 + 1];
    red[tid] = p0;
    __syncthreads();
    for (int s = 256; s > 0; s >>= 1) {
        if (tid < s) red[tid] += red[tid + s];
        __syncthreads();
    }
    float s0 = red[0];
    __syncthreads();
    red[tid] = p1;
    __syncthreads();
    for (int s = 256; s > 0; s >>= 1) {
        if (tid < s) red[tid] += red[tid + s];
        __syncthreads();
    }
    if (tid == 0) {
        out[0] = s0 + fc_b[0];
        out[1] = red[0] + fc_b[1];
    }
}

// ---------------- launch ---------------------------------------------------
extern "C" void kernel_launch(void* const* d_in, const int* in_sizes, int n_in,
                              void* d_out, int out_size) {
    (void)in_sizes; (void)n_in; (void)out_size;
    const float* x_s    = (const float*)d_in[0];
    const float* fc1_w  = (const float*)d_in[1];
    const float* fc1_b  = (const float*)d_in[2];
    const float* wh_w   = (const float*)d_in[3];
    const float* wh_b   = (const float*)d_in[4];
    const float* wt_w   = (const float*)d_in[5];
    const float* wt_b   = (const float*)d_in[6];
    const float* l1_w   = (const float*)d_in[7];
    const float* l1_b   = (const float*)d_in[8];
    const float* l2_w   = (const float*)d_in[9];
    const float* l2_b   = (const float*)d_in[10];
    const float* att1_w = (const float*)d_in[11];
    const float* att1_b = (const float*)d_in[12];
    const float* att2_w = (const float*)d_in[13];
    const float* att2_b = (const float*)d_in[14];
    const float* ln_g   = (const float*)d_in[15];
    const float* ln_b   = (const float*)d_in[16];
    const float* fc_w   = (const float*)d_in[17];
    const float* fc_b   = (const float*)d_in[18];
    float* out = (float*)d_out;

    static int smem_set = 0;
    if (!smem_set) {
        cudaFuncSetAttribute(k4_tc, cudaFuncAttributeMaxDynamicSharedMemorySize,
                             SMEM4_TOTAL);
        cudaFuncSetAttribute(k3_tc, cudaFuncAttributeMaxDynamicSharedMemorySize,
                             K3_SMEM);
        cudaFuncSetAttribute(k6_tc, cudaFuncAttributeMaxDynamicSharedMemorySize,
                             K6_SMEM);
        smem_set = 1;
    }

    dim3 gg(DH / 64, NN / 64);
    k1_tc<<<gg, 256>>>(x_s, fc1_w, fc1_b);
    k2_colpart<<<dim3(2, 32), 256>>>();
    k2b_colmean<<<1, DH>>>();
    k3_tc<<<gg, 256, K3_SMEM>>>(wh_w, wh_b, wt_w, wt_b);
    k4_tc<<<NN / 64, 256, SMEM4_TOTAL>>>();
    k4b_refine<<<NN / 8, 256>>>();
    k5_neigh<<<NN / 8, 256>>>();
    k6_tc<<<gg, 256, K6_SMEM>>>(l1_w, l1_b, l2_w, l2_b);
    k7_readout<<<NN / K7NODES, 256>>>(att1_w, att1_b, att2_w, att2_b);
    k8_softmax<<<1, 1024>>>();
    k9_wsum<<<dim3(4, 32), 128>>>();
    k10_final<<<1, DH>>>(ln_g, ln_b, fc_w, fc_b, out);
}

// round 4
// speedup vs baseline: 6.6118x; 1.0822x over previous
#include <cuda_runtime.h>
#include <cuda_bf16.h>
#include <math.h>
#include <float.h>
#include <stdint.h>

#define NN   8192
#define DIN  384
#define DH   512
#define KTOP 6
#define DH2  256
#define K7NODES 16
#define NCAND 24
#define BST  72
#define SCALE 0.044194173824159216f

// ---------------- scratch ---------------------------------------------------
__device__ float g_x[NN * DH];
__device__ float g_eh[NN * DH];
__device__ float g_et[NN * DH];
__device__ __nv_bfloat16 g_ehb[NN * DH];   // pre-scaled by SCALE
__device__ __nv_bfloat16 g_etb[NN * DH];
__device__ __nv_bfloat16 g_xsh[NN * DIN], g_xsl[NN * DIN];
__device__ __nv_bfloat16 g_xmh[NN * DH],  g_xml[NN * DH];
__device__ __nv_bfloat16 g_s1h[NN * DH],  g_s1l[NN * DH];
__device__ __nv_bfloat16 g_s2h[NN * DH],  g_s2l[NN * DH];
__device__ __nv_bfloat16 g_w1h[DIN * DH], g_w1l[DIN * DH];
__device__ __nv_bfloat16 g_whh[DH * DH],  g_whl[DH * DH];
__device__ __nv_bfloat16 g_wth[DH * DH],  g_wtl[DH * DH];
__device__ __nv_bfloat16 g_l1h[DH * DH],  g_l1l[DH * DH];
__device__ __nv_bfloat16 g_l2h[DH * DH],  g_l2l[DH * DH];
__device__ float g_emb[NN * DH];
__device__ float g_mean[DH];
__device__ float g_part1[32 * DH];
__device__ float g_part2[32 * DH];
__device__ float g_topkw[NN * KTOP];
__device__ int   g_topki[NN * KTOP];
__device__ int   g_candi[NN * NCAND];
__device__ float g_a[NN];
__device__ float g_Z[1];

__device__ __forceinline__ float lrelu(float v) { return v > 0.0f ? v : 0.01f * v; }

__device__ __forceinline__ float tanh_fast(float x) {
    float y;
    asm("tanh.approx.f32 %0, %1;" : "=f"(y) : "f"(x));
    return y;
}

__device__ __forceinline__ uint32_t saddr(const void* p) {
    return (uint32_t)__cvta_generic_to_shared(p);
}

__device__ __forceinline__ void ldsm4(unsigned r[4], uint32_t addr) {
    asm volatile("ldmatrix.sync.aligned.m8n8.x4.shared.b16 {%0,%1,%2,%3}, [%4];"
                 : "=r"(r[0]), "=r"(r[1]), "=r"(r[2]), "=r"(r[3]) : "r"(addr));
}

__device__ __forceinline__ void ldsm4t(unsigned r[4], uint32_t addr) {
    asm volatile("ldmatrix.sync.aligned.m8n8.x4.trans.shared.b16 {%0,%1,%2,%3}, [%4];"
                 : "=r"(r[0]), "=r"(r[1]), "=r"(r[2]), "=r"(r[3]) : "r"(addr));
}

__device__ __forceinline__ void mma_bf16(float* d, const unsigned a[4],
                                         unsigned b0, unsigned b1) {
    asm volatile("mma.sync.aligned.m16n8k16.row.col.f32.bf16.bf16.f32 "
                 "{%0,%1,%2,%3}, {%4,%5,%6,%7}, {%8,%9}, {%0,%1,%2,%3};"
                 : "+f"(d[0]), "+f"(d[1]), "+f"(d[2]), "+f"(d[3])
                 : "r"(a[0]), "r"(a[1]), "r"(a[2]), "r"(a[3]), "r"(b0), "r"(b1));
}

__device__ __forceinline__ void cpa16(uint32_t s, const void* g) {
    asm volatile("cp.async.cg.shared.global [%0], [%1], 16;" :: "r"(s), "l"(g));
}
__device__ __forceinline__ void cpa_commit() { asm volatile("cp.async.commit_group;"); }
#define CPWAIT0 asm volatile("cp.async.wait_group 0;")
#define CPWAIT1 asm volatile("cp.async.wait_group 1;")

__device__ __forceinline__ void split4(float4 v, __nv_bfloat16* hi, __nv_bfloat16* lo) {
    __nv_bfloat16 h0 = __float2bfloat16(v.x), h1 = __float2bfloat16(v.y);
    __nv_bfloat16 h2 = __float2bfloat16(v.z), h3 = __float2bfloat16(v.w);
    __nv_bfloat16 l0 = __float2bfloat16(v.x - __bfloat162float(h0));
    __nv_bfloat16 l1 = __float2bfloat16(v.y - __bfloat162float(h1));
    __nv_bfloat16 l2 = __float2bfloat16(v.z - __bfloat162float(h2));
    __nv_bfloat16 l3 = __float2bfloat16(v.w - __bfloat162float(h3));
    *(__nv_bfloat162*)(hi)     = __halves2bfloat162(h0, h1);
    *(__nv_bfloat162*)(hi + 2) = __halves2bfloat162(h2, h3);
    *(__nv_bfloat162*)(lo)     = __halves2bfloat162(l0, l1);
    *(__nv_bfloat162*)(lo + 2) = __halves2bfloat162(l2, l3);
}

// ---------------- K0: split fp32 -> bf16 hi/lo -----------------------------
__global__ void ksplit(const float* __restrict__ src, __nv_bfloat16* __restrict__ hi,
                       __nv_bfloat16* __restrict__ lo, int n4) {
    int i = blockIdx.x * 256 + threadIdx.x;
    if (i < n4) {
        float4 v = ((const float4*)src)[i];
        split4(v, hi + (size_t)i * 4, lo + (size_t)i * 4);
    }
}

// ---------------- K2c: xm = (x + mean)*0.5, split --------------------------
__global__ void k2c_xm() {
    int i = blockIdx.x * 256 + threadIdx.x;   // over NN*DH/4
    float4 v = ((const float4*)g_x)[i];
    int c = (i * 4) & (DH - 1);
    float4 mu = *(const float4*)&g_mean[c];
    v.x = (v.x + mu.x) * 0.5f; v.y = (v.y + mu.y) * 0.5f;
    v.z = (v.z + mu.z) * 0.5f; v.w = (v.w + mu.w) * 0.5f;
    split4(v, g_xmh + (size_t)i * 4, g_xml + (size_t)i * 4);
}

// ---------------- tile loader (64x64 bf16 via cp.async) --------------------
__device__ __forceinline__ void load_tile64(uint32_t sbase, const __nv_bfloat16* g,
                                            int gstride) {
    int tid = threadIdx.x;
#pragma unroll
    for (int j = 0; j < 2; j++) {
        int u = tid + j * 256;
        int row = u >> 3, seg = (u & 7) * 8;
        cpa16(sbase + (row * BST + seg) * 2, g + (size_t)row * gstride + seg);
    }
}

// ---------------- K1: x = lrelu(x_s @ fc1_w + fc1_b) -----------------------
#define K1_SMEM (2 * 4 * 64 * BST * 2)
__global__ void __launch_bounds__(256) k1_tc(const float* __restrict__ bias) {
    extern __shared__ char sm1[];
    uint32_t base = saddr(sm1);
    const int TB = 64 * BST * 2;
    int bm = blockIdx.y * 64, bn = blockIdx.x * 64;
    int tid = threadIdx.x, warp = tid >> 5, lane = tid & 31;
    int wm = warp & 1, wn = warp >> 1;
    int lrow = lane & 15, lkoff = (lane >> 4) * 8;
    float acc[2][2][4] = {};
    const int NCH = DIN / 64;

    auto issue = [&](int c, int s) {
        load_tile64(base + (s * 4 + 0) * TB, g_xsh + (size_t)bm * DIN + c * 64, DIN);
        load_tile64(base + (s * 4 + 1) * TB, g_xsl + (size_t)bm * DIN + c * 64, DIN);
        load_tile64(base + (s * 4 + 2) * TB, g_w1h + (size_t)(c * 64) * DH + bn, DH);
        load_tile64(base + (s * 4 + 3) * TB, g_w1l + (size_t)(c * 64) * DH + bn, DH);
        cpa_commit();
    };
    issue(0, 0);
    for (int c = 0; c < NCH; c++) {
        if (c + 1 < NCH) { issue(c + 1, (c + 1) & 1); CPWAIT1; } else { CPWAIT0; }
        __syncthreads();
        int s = c & 1;
        uint32_t Ah = base + (s * 4 + 0) * TB, Al = base + (s * 4 + 1) * TB;
        uint32_t Bh = base + (s * 4 + 2) * TB, Bl = base + (s * 4 + 3) * TB;
#pragma unroll
        for (int ks = 0; ks < 4; ks++) {
            unsigned ah[2][4], al[2][4], ph[4], pl[4];
            int aoff = ((wm * 32 + lrow) * BST + ks * 16 + lkoff) * 2;
            ldsm4(ah[0], Ah + aoff);
            ldsm4(ah[1], Ah + aoff + 16 * BST * 2);
            ldsm4(al[0], Al + aoff);
            ldsm4(al[1], Al + aoff + 16 * BST * 2);
            int boff = ((ks * 16 + (lane & 7) + 8 * ((lane >> 3) & 1)) * BST +
                        wn * 16 + 8 * (lane >> 4)) * 2;
            ldsm4t(ph, Bh + boff);
            ldsm4t(pl, Bl + boff);
#pragma unroll
            for (int m = 0; m < 2; m++)
#pragma unroll
                for (int n = 0; n < 2; n++) {
                    mma_bf16(acc[m][n], ah[m], ph[n * 2], ph[n * 2 + 1]);
                    mma_bf16(acc[m][n], ah[m], pl[n * 2], pl[n * 2 + 1]);
                    mma_bf16(acc[m][n], al[m], ph[n * 2], ph[n * 2 + 1]);
                }
        }
        __syncthreads();
    }
#pragma unroll
    for (int m = 0; m < 2; m++)
#pragma unroll
        for (int n = 0; n < 2; n++) {
            int row = bm + wm * 32 + m * 16 + (lane >> 2);
            int col = bn + wn * 16 + n * 8 + (lane & 3) * 2;
            g_x[(size_t)row * DH + col]           = lrelu(acc[m][n][0] + bias[col]);
            g_x[(size_t)row * DH + col + 1]       = lrelu(acc[m][n][1] + bias[col + 1]);
            g_x[(size_t)(row + 8) * DH + col]     = lrelu(acc[m][n][2] + bias[col]);
            g_x[(size_t)(row + 8) * DH + col + 1] = lrelu(acc[m][n][3] + bias[col + 1]);
        }
}

// ---------------- K2: column mean ------------------------------------------
__global__ void k2_colpart() {
    int c = blockIdx.x * 256 + threadIdx.x;
    int r0 = blockIdx.y * 256;
    float s = 0.0f;
    for (int i = 0; i < 256; i++) s += g_x[(r0 + i) * DH + c];
    g_part1[blockIdx.y * DH + c] = s;
}
__global__ void k2b_colmean() {
    int c = threadIdx.x;
    float s = 0.0f;
    for (int p = 0; p < 32; p++) s += g_part1[p * DH + c];
    g_mean[c] = s * (1.0f / NN);
}

// ---------------- K3: dual GEMM e_h / e_t ----------------------------------
#define K3_SMEM (2 * 6 * 64 * BST * 2)
__global__ void __launch_bounds__(256) k3_tc(const float* __restrict__ b1,
                                             const float* __restrict__ b2) {
    extern __shared__ char sm3[];
    uint32_t base = saddr(sm3);
    const int TB = 64 * BST * 2;
    int bm = blockIdx.y * 64, bn = blockIdx.x * 64;
    int tid = threadIdx.x, warp = tid >> 5, lane = tid & 31;
    int wm = warp & 1, wn = warp >> 1;
    int lrow = lane & 15, lkoff = (lane >> 4) * 8;
    float acc1[2][2][4] = {}, acc2[2][2][4] = {};
    const int NCH = DH / 64;

    auto issue = [&](int c, int s) {
        load_tile64(base + (s * 6 + 0) * TB, g_xmh + (size_t)bm * DH + c * 64, DH);
        load_tile64(base + (s * 6 + 1) * TB, g_xml + (size_t)bm * DH + c * 64, DH);
        load_tile64(base + (s * 6 + 2) * TB, g_whh + (size_t)(c * 64) * DH + bn, DH);
        load_tile64(base + (s * 6 + 3) * TB, g_whl + (size_t)(c * 64) * DH + bn, DH);
        load_tile64(base + (s * 6 + 4) * TB, g_wth + (size_t)(c * 64) * DH + bn, DH);
        load_tile64(base + (s * 6 + 5) * TB, g_wtl + (size_t)(c * 64) * DH + bn, DH);
        cpa_commit();
    };
    issue(0, 0);
    for (int c = 0; c < NCH; c++) {
        if (c + 1 < NCH) { issue(c + 1, (c + 1) & 1); CPWAIT1; } else { CPWAIT0; }
        __syncthreads();
        int s = c & 1;
        uint32_t Ah = base + (s * 6 + 0) * TB, Al = base + (s * 6 + 1) * TB;
        uint32_t B1h = base + (s * 6 + 2) * TB, B1l = base + (s * 6 + 3) * TB;
        uint32_t B2h = base + (s * 6 + 4) * TB, B2l = base + (s * 6 + 5) * TB;
#pragma unroll
        for (int ks = 0; ks < 4; ks++) {
            unsigned ah[2][4], al[2][4], p1h[4], p1l[4], p2h[4], p2l[4];
            int aoff = ((wm * 32 + lrow) * BST + ks * 16 + lkoff) * 2;
            ldsm4(ah[0], Ah + aoff);
            ldsm4(ah[1], Ah + aoff + 16 * BST * 2);
            ldsm4(al[0], Al + aoff);
            ldsm4(al[1], Al + aoff + 16 * BST * 2);
            int boff = ((ks * 16 + (lane & 7) + 8 * ((lane >> 3) & 1)) * BST +
                        wn * 16 + 8 * (lane >> 4)) * 2;
            ldsm4t(p1h, B1h + boff);
            ldsm4t(p1l, B1l + boff);
            ldsm4t(p2h, B2h + boff);
            ldsm4t(p2l, B2l + boff);
#pragma unroll
            for (int m = 0; m < 2; m++)
#pragma unroll
                for (int n = 0; n < 2; n++) {
                    mma_bf16(acc1[m][n], ah[m], p1h[n * 2], p1h[n * 2 + 1]);
                    mma_bf16(acc1[m][n], ah[m], p1l[n * 2], p1l[n * 2 + 1]);
                    mma_bf16(acc1[m][n], al[m], p1h[n * 2], p1h[n * 2 + 1]);
                    mma_bf16(acc2[m][n], ah[m], p2h[n * 2], p2h[n * 2 + 1]);
                    mma_bf16(acc2[m][n], ah[m], p2l[n * 2], p2l[n * 2 + 1]);
                    mma_bf16(acc2[m][n], al[m], p2h[n * 2], p2h[n * 2 + 1]);
                }
        }
        __syncthreads();
    }
#pragma unroll
    for (int m = 0; m < 2; m++)
#pragma unroll
        for (int n = 0; n < 2; n++) {
            int row = bm + wm * 32 + m * 16 + (lane >> 2);
            int col = bn + wn * 16 + n * 8 + (lane & 3) * 2;
            float v0 = acc1[m][n][0] + b1[col], v1 = acc1[m][n][1] + b1[col + 1];
            float v2 = acc1[m][n][2] + b1[col], v3 = acc1[m][n][3] + b1[col + 1];
            g_eh[(size_t)row * DH + col] = v0;       g_eh[(size_t)row * DH + col + 1] = v1;
            g_eh[(size_t)(row + 8) * DH + col] = v2; g_eh[(size_t)(row + 8) * DH + col + 1] = v3;
            g_ehb[(size_t)row * DH + col] = __float2bfloat16(v0 * SCALE);
            g_ehb[(size_t)row * DH + col + 1] = __float2bfloat16(v1 * SCALE);
            g_ehb[(size_t)(row + 8) * DH + col] = __float2bfloat16(v2 * SCALE);
            g_ehb[(size_t)(row + 8) * DH + col + 1] = __float2bfloat16(v3 * SCALE);
            float w0 = acc2[m][n][0] + b2[col], w1 = acc2[m][n][1] + b2[col + 1];
            float w2 = acc2[m][n][2] + b2[col], w3 = acc2[m][n][3] + b2[col + 1];
            g_et[(size_t)row * DH + col] = w0;       g_et[(size_t)row * DH + col + 1] = w1;
            g_et[(size_t)(row + 8) * DH + col] = w2; g_et[(size_t)(row + 8) * DH + col + 1] = w3;
            g_etb[(size_t)row * DH + col] = __float2bfloat16(w0);
            g_etb[(size_t)row * DH + col + 1] = __float2bfloat16(w1);
            g_etb[(size_t)(row + 8) * DH + col] = __float2bfloat16(w2);
            g_etb[(size_t)(row + 8) * DH + col + 1] = __float2bfloat16(w3);
        }
}

// ---------------- K4: score GEMM + candidate top-6 (3-stage pipeline) ------
#define ASTRIDE 520
#define B4STRIDE 136
#define SSTRIDE 132
#define SMEM_A_BYTES (64 * ASTRIDE * 2)
#define B4_CHUNK_BYTES (128 * B4STRIDE * 2)
#define SMEM_S_BYTES (64 * SSTRIDE * 4)
#define SMEM4_TOTAL (SMEM_A_BYTES + 3 * B4_CHUNK_BYTES + SMEM_S_BYTES)

__global__ void __launch_bounds__(256, 1) k4_tc() {
    extern __shared__ char sm4[];
    __nv_bfloat16* As = (__nv_bfloat16*)sm4;
    uint32_t bbase = saddr(sm4) + SMEM_A_BYTES;
    float* Ssc = (float*)(sm4 + SMEM_A_BYTES + 3 * B4_CHUNK_BYTES);

    int tid = threadIdx.x;
    int warp = tid >> 5, lane = tid & 31;
    int wm = warp & 1, wn = warp >> 1;
    int bm = blockIdx.x * 64;
    int lrow = lane & 15, lkoff = (lane >> 4) * 8;
    int myrow = tid >> 2, myq = tid & 3;

    int ldrow = tid >> 1, ldseg = (tid & 1) * 64;
    uint32_t ldoff = (uint32_t)(ldrow * B4STRIDE + ldseg) * 2;

    auto issueB = [&](int q) {
        int st = q % 3;
        int tile = q >> 2, kc = q & 3;
        const __nv_bfloat16* src =
            g_etb + (size_t)(tile * 128 + ldrow) * DH + kc * 128 + ldseg;
        uint32_t dst = bbase + st * B4_CHUNK_BYTES + ldoff;
#pragma unroll
        for (int j = 0; j < 8; j++) cpa16(dst + j * 16, src + j * 8);
        cpa_commit();
    };

    issueB(0);
    issueB(1);

    for (int i = tid; i < 64 * 64; i += 256) {
        int row = i >> 6, c4 = i & 63;
        *(uint4*)(As + row * ASTRIDE + c4 * 8) =
            *(const uint4*)(g_ehb + (size_t)(bm + row) * DH + c4 * 8);
    }

    float tv[KTOP];
    int ti[KTOP];
#pragma unroll
    for (int k = 0; k < KTOP; k++) { tv[k] = -FLT_MAX; ti[k] = 0; }

    float acc[2][4][4];
    for (int q = 0; q < 256; q++) {
        if (q < 255) { CPWAIT1; } else { CPWAIT0; }
        __syncthreads();
        if (q < 254) issueB(q + 2);
        if ((q & 3) == 0) {
#pragma unroll
            for (int a = 0; a < 2; a++)
#pragma unroll
                for (int b = 0; b < 4; b++)
#pragma unroll
                    for (int c = 0; c < 4; c++) acc[a][b][c] = 0.0f;
        }
        uint32_t Bs = bbase + (q % 3) * B4_CHUNK_BYTES;
        int ch = q & 3;
#pragma unroll
        for (int ks = 0; ks < 8; ks++) {
            unsigned a0[4], a1[4], b0[4], b1[4];
            int kA = ch * 128 + ks * 16 + lkoff;
            ldsm4(a0, saddr(&As[(wm * 32 + lrow) * ASTRIDE + kA]));
            ldsm4(a1, saddr(&As[(wm * 32 + 16 + lrow) * ASTRIDE + kA]));
            uint32_t kB = (uint32_t)((wn * 32 + lrow) * B4STRIDE + ks * 16 + lkoff) * 2;
            ldsm4(b0, Bs + kB);
            ldsm4(b1, Bs + kB + 16 * B4STRIDE * 2);
            mma_bf16(acc[0][0], a0, b0[0], b0[2]);
            mma_bf16(acc[0][1], a0, b0[1], b0[3]);
            mma_bf16(acc[0][2], a0, b1[0], b1[2]);
            mma_bf16(acc[0][3], a0, b1[1], b1[3]);
            mma_bf16(acc[1][0], a1, b0[0], b0[2]);
            mma_bf16(acc[1][1], a1, b0[1], b0[3]);
            mma_bf16(acc[1][2], a1, b1[0], b1[2]);
            mma_bf16(acc[1][3], a1, b1[1], b1[3]);
        }
        if ((q & 3) == 3) {
            int g = lane >> 2, tg = lane & 3;
#pragma unroll
            for (int msub = 0; msub < 2; msub++) {
                int row0 = wm * 32 + msub * 16 + g;
#pragma unroll
                for (int nsub = 0; nsub < 4; nsub++) {
                    int col = wn * 32 + nsub * 8 + tg * 2;
                    Ssc[row0 * SSTRIDE + col]           = acc[msub][nsub][0];
                    Ssc[row0 * SSTRIDE + col + 1]       = acc[msub][nsub][1];
                    Ssc[(row0 + 8) * SSTRIDE + col]     = acc[msub][nsub][2];
                    Ssc[(row0 + 8) * SSTRIDE + col + 1] = acc[msub][nsub][3];
                }
            }
            __syncthreads();
            int bn = (q >> 2) * 128;
#pragma unroll 1
            for (int j = 0; j < 32; j++) {
                float v = Ssc[myrow * SSTRIDE + myq * 32 + j];
                if (v > tv[KTOP - 1]) {
                    tv[KTOP - 1] = v;
                    ti[KTOP - 1] = bn + myq * 32 + j;
#pragma unroll
                    for (int p = KTOP - 1; p > 0; p--) {
                        if (tv[p] > tv[p - 1]) {
                            float tf = tv[p]; tv[p] = tv[p - 1]; tv[p - 1] = tf;
                            int tt = ti[p]; ti[p] = ti[p - 1]; ti[p - 1] = tt;
                        }
                    }
                }
            }
        }
    }
#pragma unroll
    for (int k = 0; k < KTOP; k++)
        g_candi[(size_t)(bm + myrow) * NCAND + myq * KTOP + k] = ti[k];
}

// ---------------- K4b: exact fp32 refinement -------------------------------
__global__ void __launch_bounds__(256) k4b_refine() {
    int node = blockIdx.x * 8 + (threadIdx.x >> 5);
    int lane = threadIdx.x & 31;

    float eh[16];
#pragma unroll
    for (int t = 0; t < 16; t++) eh[t] = g_eh[(size_t)node * DH + lane + t * 32];

    float vals[NCAND];
    int idxs[NCAND];
#pragma unroll
    for (int c = 0; c < NCAND; c++) {
        int idx = g_candi[(size_t)node * NCAND + c];
        idxs[c] = idx;
        const float* et = g_et + (size_t)idx * DH;
        float s = 0.0f;
#pragma unroll
        for (int t = 0; t < 16; t++) s += eh[t] * et[lane + t * 32];
#pragma unroll
        for (int o = 16; o > 0; o >>= 1) s += __shfl_xor_sync(0xffffffffu, s, o);
        vals[c] = s * SCALE;
    }

    unsigned used = 0;
#pragma unroll
    for (int p = 0; p < KTOP; p++) {
        float bv = -FLT_MAX; int bi = 0x7fffffff; int bc = 0;
#pragma unroll
        for (int c = 0; c < NCAND; c++) {
            if (!((used >> c) & 1u)) {
                if (vals[c] > bv || (vals[c] == bv && idxs[c] < bi)) {
                    bv = vals[c]; bi = idxs[c]; bc = c;
                }
            }
        }
        used |= 1u << bc;
        if (lane == 0) {
            g_topkw[node * KTOP + p] = bv;
            g_topki[node * KTOP + p] = bi;
        }
    }
}

// ---------------- K5: neighbor aggregation -> split s1,s2 ------------------
__global__ void __launch_bounds__(256) k5_neigh() {
    int node = (blockIdx.x * 256 + threadIdx.x) >> 5;
    int lane = threadIdx.x & 31;
    if (node >= NN) return;

    float w[KTOP];
    int idx[KTOP];
#pragma unroll
    for (int k = 0; k < KTOP; k++) {
        w[k] = g_topkw[node * KTOP + k];
        idx[k] = g_topki[node * KTOP + k];
    }
    float p[KTOP], ps = 0.0f;
#pragma unroll
    for (int k = 0; k < KTOP; k++) { p[k] = __expf(w[k] - w[0]); ps += p[k]; }
    float pinv = 1.0f / ps;
#pragma unroll
    for (int k = 0; k < KTOP; k++) p[k] *= pinv;

    float ehv[16], nb[KTOP][16];
#pragma unroll
    for (int t = 0; t < 16; t++) ehv[t] = g_eh[node * DH + lane + t * 32];
#pragma unroll
    for (int k = 0; k < KTOP; k++)
#pragma unroll
        for (int t = 0; t < 16; t++)
            nb[k][t] = g_et[idx[k] * DH + lane + t * 32];

    float ka[KTOP];
#pragma unroll
    for (int k = 0; k < KTOP; k++) {
        float s = 0.0f;
#pragma unroll
        for (int t = 0; t < 16; t++) {
            float ehr  = p[k] * nb[k][t] + (1.0f - p[k]) * ehv[t];
            float gate = tanh_fast(ehv[t] + ehr);
            s += nb[k][t] * gate;
        }
#pragma unroll
        for (int o = 16; o > 0; o >>= 1) s += __shfl_xor_sync(0xffffffffu, s, o);
        ka[k] = s;
    }
    float km = ka[0];
#pragma unroll
    for (int k = 1; k < KTOP; k++) km = fmaxf(km, ka[k]);
    float kp[KTOP], ks = 0.0f;
#pragma unroll
    for (int k = 0; k < KTOP; k++) { kp[k] = __expf(ka[k] - km); ks += kp[k]; }
    float kinv = 1.0f / ks;
#pragma unroll
    for (int k = 0; k < KTOP; k++) kp[k] *= kinv;

#pragma unroll
    for (int t = 0; t < 16; t++) {
        float enh = 0.0f;
#pragma unroll
        for (int k = 0; k < KTOP; k++) enh += kp[k] * nb[k][t];
        size_t d = (size_t)node * DH + lane + t * 32;
        float s1v = ehv[t] + enh;
        float s2v = ehv[t] * enh;
        __nv_bfloat16 h1 = __float2bfloat16(s1v);
        __nv_bfloat16 h2 = __float2bfloat16(s2v);
        g_s1h[d] = h1; g_s1l[d] = __float2bfloat16(s1v - __bfloat162float(h1));
        g_s2h[d] = h2; g_s2l[d] = __float2bfloat16(s2v - __bfloat162float(h2));
    }
}

// ---------------- K6: emb = lrelu(s1@l1+b1)+lrelu(s2@l2+b2) ----------------
#define K6_SMEM (2 * 8 * 64 * BST * 2)
__global__ void __launch_bounds__(256) k6_tc(const float* __restrict__ b1,
                                             const float* __restrict__ b2) {
    extern __shared__ char sm6[];
    uint32_t base = saddr(sm6);
    const int TB = 64 * BST * 2;
    int bm = blockIdx.y * 64, bn = blockIdx.x * 64;
    int tid = threadIdx.x, warp = tid >> 5, lane = tid & 31;
    int wm = warp & 1, wn = warp >> 1;
    int lrow = lane & 15, lkoff = (lane >> 4) * 8;
    float acc1[2][2][4] = {}, acc2[2][2][4] = {};
    const int NCH = DH / 64;

    auto issue = [&](int c, int s) {
        load_tile64(base + (s * 8 + 0) * TB, g_s1h + (size_t)bm * DH + c * 64, DH);
        load_tile64(base + (s * 8 + 1) * TB, g_s1l + (size_t)bm * DH + c * 64, DH);
        load_tile64(base + (s * 8 + 2) * TB, g_s2h + (size_t)bm * DH + c * 64, DH);
        load_tile64(base + (s * 8 + 3) * TB, g_s2l + (size_t)bm * DH + c * 64, DH);
        load_tile64(base + (s * 8 + 4) * TB, g_l1h + (size_t)(c * 64) * DH + bn, DH);
        load_tile64(base + (s * 8 + 5) * TB, g_l1l + (size_t)(c * 64) * DH + bn, DH);
        load_tile64(base + (s * 8 + 6) * TB, g_l2h + (size_t)(c * 64) * DH + bn, DH);
        load_tile64(base + (s * 8 + 7) * TB, g_l2l + (size_t)(c * 64) * DH + bn, DH);
        cpa_commit();
    };
    issue(0, 0);
    for (int c = 0; c < NCH; c++) {
        if (c + 1 < NCH) { issue(c + 1, (c + 1) & 1); CPWAIT1; } else { CPWAIT0; }
        __syncthreads();
        int s = c & 1;
        uint32_t A1h = base + (s * 8 + 0) * TB, A1l = base + (s * 8 + 1) * TB;
        uint32_t A2h = base + (s * 8 + 2) * TB, A2l = base + (s * 8 + 3) * TB;
        uint32_t B1h = base + (s * 8 + 4) * TB, B1l = base + (s * 8 + 5) * TB;
        uint32_t B2h = base + (s * 8 + 6) * TB, B2l = base + (s * 8 + 7) * TB;
#pragma unroll
        for (int ks = 0; ks < 4; ks++) {
            unsigned a1h[2][4], a1l[2][4], a2h[2][4], a2l[2][4];
            int aoff = ((wm * 32 + lrow) * BST + ks * 16 + lkoff) * 2;
            ldsm4(a1h[0], A1h + aoff); ldsm4(a1h[1], A1h + aoff + 16 * BST * 2);
            ldsm4(a1l[0], A1l + aoff); ldsm4(a1l[1], A1l + aoff + 16 * BST * 2);
            ldsm4(a2h[0], A2h + aoff); ldsm4(a2h[1], A2h + aoff + 16 * BST * 2);
            ldsm4(a2l[0], A2l + aoff); ldsm4(a2l[1], A2l + aoff + 16 * BST * 2);
            int boff = ((ks * 16 + (lane & 7) + 8 * ((lane >> 3) & 1)) * BST +
                        wn * 16 + 8 * (lane >> 4)) * 2;
            unsigned p1h[4], p1l[4], p2h[4], p2l[4];
            ldsm4t(p1h, B1h + boff);
            ldsm4t(p1l, B1l + boff);
            ldsm4t(p2h, B2h + boff);
            ldsm4t(p2l, B2l + boff);
#pragma unroll
            for (int m = 0; m < 2; m++)
#pragma unroll
                for (int n = 0; n < 2; n++) {
                    mma_bf16(acc1[m][n], a1h[m], p1h[n * 2], p1h[n * 2 + 1]);
                    mma_bf16(acc1[m][n], a1h[m], p1l[n * 2], p1l[n * 2 + 1]);
                    mma_bf16(acc1[m][n], a1l[m], p1h[n * 2], p1h[n * 2 + 1]);
                    mma_bf16(acc2[m][n], a2h[m], p2h[n * 2], p2h[n * 2 + 1]);
                    mma_bf16(acc2[m][n], a2h[m], p2l[n * 2], p2l[n * 2 + 1]);
                    mma_bf16(acc2[m][n], a2l[m], p2h[n * 2], p2h[n * 2 + 1]);
                }
        }
        __syncthreads();
    }
#pragma unroll
    for (int m = 0; m < 2; m++)
#pragma unroll
        for (int n = 0; n < 2; n++) {
            int row = bm + wm * 32 + m * 16 + (lane >> 2);
            int col = bn + wn * 16 + n * 8 + (lane & 3) * 2;
            g_emb[(size_t)row * DH + col] =
                lrelu(acc1[m][n][0] + b1[col]) + lrelu(acc2[m][n][0] + b2[col]);
            g_emb[(size_t)row * DH + col + 1] =
                lrelu(acc1[m][n][1] + b1[col + 1]) + lrelu(acc2[m][n][1] + b2[col + 1]);
            g_emb[(size_t)(row + 8) * DH + col] =
                lrelu(acc1[m][n][2] + b1[col]) + lrelu(acc2[m][n][2] + b2[col]);
            g_emb[(size_t)(row + 8) * DH + col + 1] =
                lrelu(acc1[m][n][3] + b1[col + 1]) + lrelu(acc2[m][n][3] + b2[col + 1]);
        }
}

// ---------------- K7: node scores ------------------------------------------
__global__ void k7_readout(const float* __restrict__ att1_w, const float* __restrict__ att1_b,
                           const float* __restrict__ att2_w, const float* __restrict__ att2_b) {
    __shared__ float se[K7NODES][DH];
    __shared__ float warpred[8];
    int n0 = blockIdx.x * K7NODES;
    int tid = threadIdx.x;
    for (int i = tid; i < K7NODES * DH; i += 256)
        se[i >> 9][i & 511] = g_emb[(n0 + (i >> 9)) * DH + (i & 511)];
    __syncthreads();

    int j = tid;
    float acc[K7NODES];
#pragma unroll
    for (int m = 0; m < K7NODES; m++) acc[m] = 0.0f;

    for (int d = 0; d < DH; d += 4) {
        float w0 = att1_w[(d + 0) * DH2 + j];
        float w1 = att1_w[(d + 1) * DH2 + j];
        float w2 = att1_w[(d + 2) * DH2 + j];
        float w3 = att1_w[(d + 3) * DH2 + j];
#pragma unroll
        for (int m = 0; m < K7NODES; m++) {
            float4 e = *(const float4*)&se[m][d];
            acc[m] += e.x * w0 + e.y * w1 + e.z * w2 + e.w * w3;
        }
    }
    float b1 = att1_b[j], a2 = att2_w[j], b2v = att2_b[0];
    int lane = tid & 31, wid = tid >> 5;
    for (int m = 0; m < K7NODES; m++) {
        float v = lrelu(acc[m] + b1) * a2;
#pragma unroll
        for (int o = 16; o > 0; o >>= 1) v += __shfl_xor_sync(0xffffffffu, v, o);
        if (lane == 0) warpred[wid] = v;
        __syncthreads();
        if (tid == 0) {
            float s = 0.0f;
            for (int q = 0; q < 8; q++) s += warpred[q];
            g_a[n0 + m] = s + b2v;
        }
        __syncthreads();
    }
}

// ---------------- K8: softmax over nodes -----------------------------------
__global__ void k8_softmax() {
    __shared__ float red[1024];
    int tid = threadIdx.x;
    float lm = -FLT_MAX;
    for (int i = tid; i < NN; i += 1024) lm = fmaxf(lm, g_a[i]);
    red[tid] = lm;
    __syncthreads();
    for (int s = 512; s > 0; s >>= 1) {
        if (tid < s) red[tid] = fmaxf(red[tid], red[tid + s]);
        __syncthreads();
    }
    float amax = red[0];
    __syncthreads();
    float ls = 0.0f;
    for (int i = tid; i < NN; i += 1024) {
        float w = expf(g_a[i] - amax);
        g_a[i] = w;
        ls += w;
    }
    red[tid] = ls;
    __syncthreads();
    for (int s = 512; s > 0; s >>= 1) {
        if (tid < s) red[tid] += red[tid + s];
        __syncthreads();
    }
    if (tid == 0) g_Z[0] = red[0];
}

// ---------------- K9: weighted partial sums --------------------------------
__global__ void k9_wsum() {
    int d = blockIdx.x * 128 + threadIdx.x;
    int r0 = blockIdx.y * 256;
    float s = 0.0f;
    for (int i = 0; i < 256; i++) s += g_a[r0 + i] * g_emb[(r0 + i) * DH + d];
    g_part2[blockIdx.y * DH + d] = s;
}

// ---------------- K10: finalize --------------------------------------------
__global__ void k10_final(const float* __restrict__ ln_g, const float* __restrict__ ln_b,
                          const float* __restrict__ fc_w, const float* __restrict__ fc_b,
                          float* __restrict__ out) {
    __shared__ float red[DH];
    int tid = threadIdx.x;
    float raw = 0.0f;
    for (int p = 0; p < 32; p++) raw += g_part2[p * DH + tid];
    float h = raw / g_Z[0];

    red[tid] = h;
    __syncthreads();
    for (int s = 256; s > 0; s >>= 1) {
        if (tid < s) red[tid] += red[tid + s];
        __syncthreads();
    }
    float mu = red[0] * (1.0f / DH);
    __syncthreads();
    float dv = h - mu;
    red[tid] = dv * dv;
    __syncthreads();
    for (int s = 256; s > 0; s >>= 1) {
        if (tid < s) red[tid] += red[tid + s];
        __syncthreads();
    }
    float var = red[0] * (1.0f / DH);
    __syncthreads();
    float hn = dv * rsqrtf(var + 1e-5f) * ln_g[tid] + ln_b[tid];

    float p0 = hn * fc_w[tid * 2 + 0];
    float p1 = hn * fc_w[tid * 2 + 1];
    red[tid] = p0;
    __syncthreads();
    for (int s = 256; s > 0; s >>= 1) {
        if (tid < s) red[tid] += red[tid + s];
        __syncthreads();
    }
    float s0 = red[0];
    __syncthreads();
    red[tid] = p1;
    __syncthreads();
    for (int s = 256; s > 0; s >>= 1) {
        if (tid < s) red[tid] += red[tid + s];
        __syncthreads();
    }
    if (tid == 0) {
        out[0] = s0 + fc_b[0];
        out[1] = red[0] + fc_b[1];
    }
}

// ---------------- launch ---------------------------------------------------
extern "C" void kernel_launch(void* const* d_in, const int* in_sizes, int n_in,
                              void* d_out, int out_size) {
    (void)in_sizes; (void)n_in; (void)out_size;
    const float* x_s    = (const float*)d_in[0];
    const float* fc1_w  = (const float*)d_in[1];
    const float* fc1_b  = (const float*)d_in[2];
    const float* wh_w   = (const float*)d_in[3];
    const float* wh_b   = (const float*)d_in[4];
    const float* wt_w   = (const float*)d_in[5];
    const float* wt_b   = (const float*)d_in[6];
    const float* l1_w   = (const float*)d_in[7];
    const float* l1_b   = (const float*)d_in[8];
    const float* l2_w   = (const float*)d_in[9];
    const float* l2_b   = (const float*)d_in[10];
    const float* att1_w = (const float*)d_in[11];
    const float* att1_b = (const float*)d_in[12];
    const float* att2_w = (const float*)d_in[13];
    const float* att2_b = (const float*)d_in[14];
    const float* ln_g   = (const float*)d_in[15];
    const float* ln_b   = (const float*)d_in[16];
    const float* fc_w   = (const float*)d_in[17];
    const float* fc_b   = (const float*)d_in[18];
    float* out = (float*)d_out;

    static int smem_set = 0;
    if (!smem_set) {
        cudaFuncSetAttribute(k4_tc, cudaFuncAttributeMaxDynamicSharedMemorySize, SMEM4_TOTAL);
        cudaFuncSetAttribute(k1_tc, cudaFuncAttributeMaxDynamicSharedMemorySize, K1_SMEM);
        cudaFuncSetAttribute(k3_tc, cudaFuncAttributeMaxDynamicSharedMemorySize, K3_SMEM);
        cudaFuncSetAttribute(k6_tc, cudaFuncAttributeMaxDynamicSharedMemorySize, K6_SMEM);
        smem_set = 1;
    }

    __nv_bfloat16 *d_w1h, *d_w1l, *d_whh, *d_whl, *d_wth, *d_wtl;
    __nv_bfloat16 *d_l1h, *d_l1l, *d_l2h, *d_l2l, *d_xsh, *d_xsl;
    cudaGetSymbolAddress((void**)&d_w1h, g_w1h); cudaGetSymbolAddress((void**)&d_w1l, g_w1l);
    cudaGetSymbolAddress((void**)&d_whh, g_whh); cudaGetSymbolAddress((void**)&d_whl, g_whl);
    cudaGetSymbolAddress((void**)&d_wth, g_wth); cudaGetSymbolAddress((void**)&d_wtl, g_wtl);
    cudaGetSymbolAddress((void**)&d_l1h, g_l1h); cudaGetSymbolAddress((void**)&d_l1l, g_l1l);
    cudaGetSymbolAddress((void**)&d_l2h, g_l2h); cudaGetSymbolAddress((void**)&d_l2l, g_l2l);
    cudaGetSymbolAddress((void**)&d_xsh, g_xsh); cudaGetSymbolAddress((void**)&d_xsl, g_xsl);

    ksplit<<<(NN * DIN / 4 + 255) / 256, 256>>>(x_s, d_xsh, d_xsl, NN * DIN / 4);
    ksplit<<<(DIN * DH / 4 + 255) / 256, 256>>>(fc1_w, d_w1h, d_w1l, DIN * DH / 4);
    ksplit<<<(DH * DH / 4 + 255) / 256, 256>>>(wh_w, d_whh, d_whl, DH * DH / 4);
    ksplit<<<(DH * DH / 4 + 255) / 256, 256>>>(wt_w, d_wth, d_wtl, DH * DH / 4);
    ksplit<<<(DH * DH / 4 + 255) / 256, 256>>>(l1_w, d_l1h, d_l1l, DH * DH / 4);
    ksplit<<<(DH * DH / 4 + 255) / 256, 256>>>(l2_w, d_l2h, d_l2l, DH * DH / 4);

    dim3 gg(DH / 64, NN / 64);
    k1_tc<<<gg, 256, K1_SMEM>>>(fc1_b);
    k2_colpart<<<dim3(2, 32), 256>>>();
    k2b_colmean<<<1, DH>>>();
    k2c_xm<<<NN * DH / 4 / 256, 256>>>();
    k3_tc<<<gg, 256, K3_SMEM>>>(wh_b, wt_b);
    k4_tc<<<NN / 64, 256, SMEM4_TOTAL>>>();
    k4b_refine<<<NN / 8, 256>>>();
    k5_neigh<<<NN / 8, 256>>>();
    k6_tc<<<gg, 256, K6_SMEM>>>(l1_b, l2_b);
    k7_readout<<<NN / K7NODES, 256>>>(att1_w, att1_b, att2_w, att2_b);
    k8_softmax<<<1, 1024>>>();
    k9_wsum<<<dim3(4, 32), 128>>>();
    k10_final<<<1, DH>>>(ln_g, ln_b, fc_w, fc_b, out);
}